// round 2
// baseline (speedup 1.0000x reference)
#include <cuda_runtime.h>
#include <cstdint>

#define B_   2
#define H_   8
#define BH   16
#define T_   2048
#define N_   1024
#define D_   128
#define TM   64
#define TS   64
#define KC   16
#define NTH  256
#define NCHUNK (N_ / KC)   // 64
#define NTT    (T_ / TM)   // 32

// RoPE'd Q scratch: 16 * 2048 * 1024 floats = 128 MiB (static device alloc — allowed)
__device__ float g_QR[(size_t)BH * T_ * N_];

// ---------------------------------------------------------------------------
// Kernel 1: RoPE.  QR[bh,t,2i]   = q0*c - q1*s
//                  QR[bh,t,2i+1] = q1*c + q0*s
// freq(n) = 2^(-16*floor(n/2)*2/N) / (2*pi);  phase = frac(t*freq)*2*pi
// ---------------------------------------------------------------------------
__global__ void rope_kernel(const float* __restrict__ Q) {
    size_t idx = (size_t)blockIdx.x * blockDim.x + threadIdx.x;  // pair index
    const size_t npairs = (size_t)BH * T_ * (N_ / 2);
    if (idx >= npairs) return;
    int    n2  = (int)(idx % (N_ / 2));
    size_t row = idx / (N_ / 2);
    int    t   = (int)(row % T_);

    float pos  = (float)(2 * n2);
    float freq = exp2f(-16.0f * pos * (1.0f / (float)N_)) * 0.15915494309189535f;
    float r    = (float)t * freq;
    float ph   = (r - floorf(r)) * 6.283185307179586f;
    float s, c;
    __sincosf(ph, &s, &c);

    const float2 q = ((const float2*)Q)[idx];
    float2 o;
    o.x = q.x * c - q.y * s;
    o.y = q.y * c + q.x * s;
    ((float2*)g_QR)[idx] = o;
}

// ---------------------------------------------------------------------------
// cp.async helper (16B, L2-cached)
// ---------------------------------------------------------------------------
__device__ __forceinline__ void cp_async16(float* smem_dst, const float* gsrc) {
    uint32_t d = (uint32_t)__cvta_generic_to_shared(smem_dst);
    asm volatile("cp.async.cg.shared.global [%0], [%1], 16;\n"
                 :: "r"(d), "l"(gsrc) : "memory");
}

// ---------------------------------------------------------------------------
// Kernel 2: O[bh, t, :] = sum_{s < t} (QR[t]·QR[s]) * V[s, :]
// One block per (bh, 64-row t-tile). Loops over s-tiles 0..tt.
// Stage A: S = Qt (64xN) @ Qs^T (double-buffered smem SGEMM, fp32)
// Stage B: O += S @ Vtile (V prefetched via cp.async)
// ---------------------------------------------------------------------------
__global__ void __launch_bounds__(NTH, 2)
attn_kernel(const float* __restrict__ V, float* __restrict__ O) {
    extern __shared__ float smem[];
    float* As = smem;                 // [2][KC][TM] = 2048 floats
    float* Bs = smem + 2 * KC * TM;   // [2][KC][TS] = 2048 floats
    float* Ss = smem + 4 * KC * TM;   // [TS][TM]    = 4096 floats
    float* Vs = Ss + TS * TM;         // [TS][D_]    = 8192 floats
    // total 16384 floats = 64 KiB

    const int bid = blockIdx.x;
    const int bh  = bid & (BH - 1);
    const int tt  = (NTT - 1) - (bid >> 4);    // heavy tiles on early bids
    const int t0  = tt * TM;

    const float* QRbh = g_QR + (size_t)bh * T_ * N_;
    const float* Vbh  = V    + (size_t)bh * T_ * D_;
    float*       Obh  = O    + (size_t)bh * T_ * D_;

    const int tid = threadIdx.x;
    const int tx  = tid & 15;
    const int ty  = tid >> 4;

    float o[4][8];
#pragma unroll
    for (int i = 0; i < 4; ++i)
#pragma unroll
        for (int j = 0; j < 8; ++j) o[i][j] = 0.0f;

    // per-thread global-load lane: row lr (0..63), 4 cols at lc within a chunk
    const int lr = tid >> 2;
    const int lc = (tid & 3) * 4;
    const float* Aglb = QRbh + (size_t)(t0 + lr) * N_ + lc;

    for (int st = 0; st <= tt; ++st) {
        const int s0 = st * TM;

        // --- kick off async V-tile load (64 x 128 fp32) ---
        {
            const float* Vg = Vbh + (size_t)s0 * D_;
#pragma unroll
            for (int i = 0; i < 8; ++i) {
                int c   = tid + i * NTH;     // 0..2047 (16B chunks)
                int row = c >> 5;            // 32 chunks per row of 128 floats
                int col = (c & 31) * 4;
                cp_async16(&Vs[row * D_ + col], Vg + (size_t)row * D_ + col);
            }
            asm volatile("cp.async.commit_group;\n" ::: "memory");
        }

        const float* Bglb = QRbh + (size_t)(s0 + lr) * N_ + lc;

        float sacc[4][4];
#pragma unroll
        for (int i = 0; i < 4; ++i)
#pragma unroll
            for (int j = 0; j < 4; ++j) sacc[i][j] = 0.0f;

        // --- Stage A: 64x64 S-tile, K = 1024, double-buffered ---
        float4 aReg = *(const float4*)Aglb;
        float4 bReg = *(const float4*)Bglb;
        int cur = 0;
        {   // store chunk 0 (transposed: [k][m])
            As[(lc + 0) * TM + lr] = aReg.x;
            As[(lc + 1) * TM + lr] = aReg.y;
            As[(lc + 2) * TM + lr] = aReg.z;
            As[(lc + 3) * TM + lr] = aReg.w;
            Bs[(lc + 0) * TS + lr] = bReg.x;
            Bs[(lc + 1) * TS + lr] = bReg.y;
            Bs[(lc + 2) * TS + lr] = bReg.z;
            Bs[(lc + 3) * TS + lr] = bReg.w;
        }
        __syncthreads();

        for (int cc = 0; cc < NCHUNK; ++cc) {
            if (cc + 1 < NCHUNK) {   // prefetch next chunk into regs
                aReg = *(const float4*)(Aglb + (cc + 1) * KC);
                bReg = *(const float4*)(Bglb + (cc + 1) * KC);
            }
            const float* Ab = As + cur * (KC * TM);
            const float* Bb = Bs + cur * (KC * TS);
#pragma unroll
            for (int k = 0; k < KC; ++k) {
                float4 a = *(const float4*)(Ab + k * TM + ty * 4);
                float4 b = *(const float4*)(Bb + k * TS + tx * 4);
                float av[4] = {a.x, a.y, a.z, a.w};
                float bv[4] = {b.x, b.y, b.z, b.w};
#pragma unroll
                for (int i = 0; i < 4; ++i)
#pragma unroll
                    for (int j = 0; j < 4; ++j)
                        sacc[i][j] = fmaf(av[i], bv[j], sacc[i][j]);
            }
            if (cc + 1 < NCHUNK) {
                float* Aw = As + (cur ^ 1) * (KC * TM);
                float* Bw = Bs + (cur ^ 1) * (KC * TS);
                Aw[(lc + 0) * TM + lr] = aReg.x;
                Aw[(lc + 1) * TM + lr] = aReg.y;
                Aw[(lc + 2) * TM + lr] = aReg.z;
                Aw[(lc + 3) * TM + lr] = aReg.w;
                Bw[(lc + 0) * TS + lr] = bReg.x;
                Bw[(lc + 1) * TS + lr] = bReg.y;
                Bw[(lc + 2) * TS + lr] = bReg.z;
                Bw[(lc + 3) * TS + lr] = bReg.w;
                __syncthreads();
                cur ^= 1;
            }
        }

        // --- mask (strict causal on diagonal tile) + stage S in smem [k'][m] ---
        const bool diag = (st == tt);
#pragma unroll
        for (int j = 0; j < 4; ++j)
#pragma unroll
            for (int i = 0; i < 4; ++i) {
                float v = sacc[i][j];
                if (diag && (tx * 4 + j) >= (ty * 4 + i)) v = 0.0f;  // keep s < t
                Ss[(tx * 4 + j) * TM + (ty * 4 + i)] = v;
            }

        asm volatile("cp.async.wait_group 0;\n" ::: "memory");
        __syncthreads();

        // --- Stage B: O(64x128) += S(64x64) @ Vtile(64x128) ---
#pragma unroll 4
        for (int k = 0; k < TS; ++k) {
            float4 a  = *(const float4*)(Ss + k * TM + ty * 4);
            float4 v0 = *(const float4*)(Vs + k * D_ + tx * 4);
            float4 v1 = *(const float4*)(Vs + k * D_ + 64 + tx * 4);
            float av[4]  = {a.x, a.y, a.z, a.w};
            float v0v[4] = {v0.x, v0.y, v0.z, v0.w};
            float v1v[4] = {v1.x, v1.y, v1.z, v1.w};
#pragma unroll
            for (int i = 0; i < 4; ++i) {
#pragma unroll
                for (int j = 0; j < 4; ++j) {
                    o[i][j]     = fmaf(av[i], v0v[j], o[i][j]);
                    o[i][j + 4] = fmaf(av[i], v1v[j], o[i][j + 4]);
                }
            }
        }
        __syncthreads();   // Ss/Vs consumed; safe for next iteration's writes
    }

    // --- writeback ---
#pragma unroll
    for (int i = 0; i < 4; ++i) {
        const int t = t0 + ty * 4 + i;
        float4 r0 = make_float4(o[i][0], o[i][1], o[i][2], o[i][3]);
        float4 r1 = make_float4(o[i][4], o[i][5], o[i][6], o[i][7]);
        *(float4*)(Obh + (size_t)t * D_ + tx * 4)      = r0;
        *(float4*)(Obh + (size_t)t * D_ + 64 + tx * 4) = r1;
    }
}

// ---------------------------------------------------------------------------
extern "C" void kernel_launch(void* const* d_in, const int* in_sizes, int n_in,
                              void* d_out, int out_size) {
    const float* Q = (const float*)d_in[0];
    const float* V = (const float*)d_in[2];   // d_in[1] is K == Q, unused
    float* O = (float*)d_out;

    const size_t npairs = (size_t)BH * T_ * (N_ / 2);
    const int rope_blocks = (int)((npairs + NTH - 1) / NTH);
    rope_kernel<<<rope_blocks, NTH>>>(Q);

    cudaFuncSetAttribute(attn_kernel,
                         cudaFuncAttributeMaxDynamicSharedMemorySize, 64 * 1024);
    attn_kernel<<<NTT * BH, NTH, 64 * 1024>>>(V, O);
}

// round 3
// speedup vs baseline: 1.0552x; 1.0552x over previous
#include <cuda_runtime.h>
#include <cstdint>

#define B_   2
#define H_   8
#define BH   16
#define T_   2048
#define N_   1024
#define D_   128
#define TM   64
#define TS   64
#define KC   16
#define NTH  256
#define NCHUNK (N_ / KC)   // 64
#define NTT    (T_ / TM)   // 32

// RoPE'd Q scratch: 16 * 2048 * 1024 floats = 128 MiB (static device alloc — allowed)
__device__ float g_QR[(size_t)BH * T_ * N_];

// ---------------------------------------------------------------------------
// Kernel 1: RoPE.  QR[bh,t,2i]   = q0*c - q1*s
//                  QR[bh,t,2i+1] = q1*c + q0*s
// freq(n) = 2^(-16*floor(n/2)*2/N) / (2*pi);  phase = frac(t*freq)*2*pi
// ---------------------------------------------------------------------------
__global__ void rope_kernel(const float* __restrict__ Q) {
    size_t idx = (size_t)blockIdx.x * blockDim.x + threadIdx.x;  // pair index
    const size_t npairs = (size_t)BH * T_ * (N_ / 2);
    if (idx >= npairs) return;
    int    n2  = (int)(idx % (N_ / 2));
    size_t row = idx / (N_ / 2);
    int    t   = (int)(row % T_);

    float pos  = (float)(2 * n2);
    float freq = exp2f(-16.0f * pos * (1.0f / (float)N_)) * 0.15915494309189535f;
    float r    = (float)t * freq;
    float ph   = (r - floorf(r)) * 6.283185307179586f;
    float s, c;
    __sincosf(ph, &s, &c);

    const float2 q = ((const float2*)Q)[idx];
    float2 o;
    o.x = q.x * c - q.y * s;
    o.y = q.y * c + q.x * s;
    ((float2*)g_QR)[idx] = o;
}

// ---------------------------------------------------------------------------
// cp.async helper (16B, L2-cached)
// ---------------------------------------------------------------------------
__device__ __forceinline__ void cp_async16(float* smem_dst, const float* gsrc) {
    uint32_t d = (uint32_t)__cvta_generic_to_shared(smem_dst);
    asm volatile("cp.async.cg.shared.global [%0], [%1], 16;\n"
                 :: "r"(d), "l"(gsrc) : "memory");
}

// ---------------------------------------------------------------------------
// Kernel 2: O[bh, t, :] = sum_{s < t} (QR[t]·QR[s]) * V[s, :]
// One block per (bh, 64-row t-tile). Loops over s-tiles 0..tt.
// Stage A: S = Qt (64xN) @ Qs^T (double-buffered smem SGEMM, fp32)
// Stage B: O += S @ Vtile (V prefetched via cp.async)
// ---------------------------------------------------------------------------
__global__ void __launch_bounds__(NTH, 2)
attn_kernel(const float* __restrict__ V, float* __restrict__ O) {
    extern __shared__ float smem[];
    float* As = smem;                 // [2][KC][TM] = 2048 floats
    float* Bs = smem + 2 * KC * TM;   // [2][KC][TS] = 2048 floats
    float* Ss = smem + 4 * KC * TM;   // [TS][TM]    = 4096 floats
    float* Vs = Ss + TS * TM;         // [TS][D_]    = 8192 floats
    // total 16384 floats = 64 KiB

    const int bid = blockIdx.x;
    const int bh  = bid & (BH - 1);
    const int tt  = (NTT - 1) - (bid >> 4);    // heavy tiles on early bids
    const int t0  = tt * TM;

    const float* QRbh = g_QR + (size_t)bh * T_ * N_;
    const float* Vbh  = V    + (size_t)bh * T_ * D_;
    float*       Obh  = O    + (size_t)bh * T_ * D_;

    const int tid = threadIdx.x;
    const int tx  = tid & 15;
    const int ty  = tid >> 4;

    float o[4][8];
#pragma unroll
    for (int i = 0; i < 4; ++i)
#pragma unroll
        for (int j = 0; j < 8; ++j) o[i][j] = 0.0f;

    // per-thread global-load lane: row lr (0..63), 4 cols at lc within a chunk
    const int lr = tid >> 2;
    const int lc = (tid & 3) * 4;
    const float* Aglb = QRbh + (size_t)(t0 + lr) * N_ + lc;

    for (int st = 0; st <= tt; ++st) {
        const int s0 = st * TM;

        // --- kick off async V-tile load (64 x 128 fp32) ---
        {
            const float* Vg = Vbh + (size_t)s0 * D_;
#pragma unroll
            for (int i = 0; i < 8; ++i) {
                int c   = tid + i * NTH;     // 0..2047 (16B chunks)
                int row = c >> 5;            // 32 chunks per row of 128 floats
                int col = (c & 31) * 4;
                cp_async16(&Vs[row * D_ + col], Vg + (size_t)row * D_ + col);
            }
            asm volatile("cp.async.commit_group;\n" ::: "memory");
        }

        const float* Bglb = QRbh + (size_t)(s0 + lr) * N_ + lc;

        float sacc[4][4];
#pragma unroll
        for (int i = 0; i < 4; ++i)
#pragma unroll
            for (int j = 0; j < 4; ++j) sacc[i][j] = 0.0f;

        // --- Stage A: 64x64 S-tile, K = 1024, double-buffered ---
        float4 aReg = *(const float4*)Aglb;
        float4 bReg = *(const float4*)Bglb;
        int cur = 0;
        {   // store chunk 0 (transposed: [k][m])
            As[(lc + 0) * TM + lr] = aReg.x;
            As[(lc + 1) * TM + lr] = aReg.y;
            As[(lc + 2) * TM + lr] = aReg.z;
            As[(lc + 3) * TM + lr] = aReg.w;
            Bs[(lc + 0) * TS + lr] = bReg.x;
            Bs[(lc + 1) * TS + lr] = bReg.y;
            Bs[(lc + 2) * TS + lr] = bReg.z;
            Bs[(lc + 3) * TS + lr] = bReg.w;
        }
        __syncthreads();

        for (int cc = 0; cc < NCHUNK; ++cc) {
            if (cc + 1 < NCHUNK) {   // prefetch next chunk into regs
                aReg = *(const float4*)(Aglb + (cc + 1) * KC);
                bReg = *(const float4*)(Bglb + (cc + 1) * KC);
            }
            const float* Ab = As + cur * (KC * TM);
            const float* Bb = Bs + cur * (KC * TS);
#pragma unroll
            for (int k = 0; k < KC; ++k) {
                float4 a = *(const float4*)(Ab + k * TM + ty * 4);
                float4 b = *(const float4*)(Bb + k * TS + tx * 4);
                float av[4] = {a.x, a.y, a.z, a.w};
                float bv[4] = {b.x, b.y, b.z, b.w};
#pragma unroll
                for (int i = 0; i < 4; ++i)
#pragma unroll
                    for (int j = 0; j < 4; ++j)
                        sacc[i][j] = fmaf(av[i], bv[j], sacc[i][j]);
            }
            if (cc + 1 < NCHUNK) {
                float* Aw = As + (cur ^ 1) * (KC * TM);
                float* Bw = Bs + (cur ^ 1) * (KC * TS);
                Aw[(lc + 0) * TM + lr] = aReg.x;
                Aw[(lc + 1) * TM + lr] = aReg.y;
                Aw[(lc + 2) * TM + lr] = aReg.z;
                Aw[(lc + 3) * TM + lr] = aReg.w;
                Bw[(lc + 0) * TS + lr] = bReg.x;
                Bw[(lc + 1) * TS + lr] = bReg.y;
                Bw[(lc + 2) * TS + lr] = bReg.z;
                Bw[(lc + 3) * TS + lr] = bReg.w;
                __syncthreads();
                cur ^= 1;
            }
        }

        // --- mask (strict causal on diagonal tile) + stage S in smem [k'][m] ---
        const bool diag = (st == tt);
#pragma unroll
        for (int j = 0; j < 4; ++j)
#pragma unroll
            for (int i = 0; i < 4; ++i) {
                float v = sacc[i][j];
                if (diag && (tx * 4 + j) >= (ty * 4 + i)) v = 0.0f;  // keep s < t
                Ss[(tx * 4 + j) * TM + (ty * 4 + i)] = v;
            }

        asm volatile("cp.async.wait_group 0;\n" ::: "memory");
        __syncthreads();

        // --- Stage B: O(64x128) += S(64x64) @ Vtile(64x128) ---
#pragma unroll 4
        for (int k = 0; k < TS; ++k) {
            float4 a  = *(const float4*)(Ss + k * TM + ty * 4);
            float4 v0 = *(const float4*)(Vs + k * D_ + tx * 4);
            float4 v1 = *(const float4*)(Vs + k * D_ + 64 + tx * 4);
            float av[4]  = {a.x, a.y, a.z, a.w};
            float v0v[4] = {v0.x, v0.y, v0.z, v0.w};
            float v1v[4] = {v1.x, v1.y, v1.z, v1.w};
#pragma unroll
            for (int i = 0; i < 4; ++i) {
#pragma unroll
                for (int j = 0; j < 4; ++j) {
                    o[i][j]     = fmaf(av[i], v0v[j], o[i][j]);
                    o[i][j + 4] = fmaf(av[i], v1v[j], o[i][j + 4]);
                }
            }
        }
        __syncthreads();   // Ss/Vs consumed; safe for next iteration's writes
    }

    // --- writeback ---
#pragma unroll
    for (int i = 0; i < 4; ++i) {
        const int t = t0 + ty * 4 + i;
        float4 r0 = make_float4(o[i][0], o[i][1], o[i][2], o[i][3]);
        float4 r1 = make_float4(o[i][4], o[i][5], o[i][6], o[i][7]);
        *(float4*)(Obh + (size_t)t * D_ + tx * 4)      = r0;
        *(float4*)(Obh + (size_t)t * D_ + 64 + tx * 4) = r1;
    }
}

// ---------------------------------------------------------------------------
extern "C" void kernel_launch(void* const* d_in, const int* in_sizes, int n_in,
                              void* d_out, int out_size) {
    const float* Q = (const float*)d_in[0];
    const float* V = (const float*)d_in[2];   // d_in[1] is K == Q, unused
    float* O = (float*)d_out;

    const size_t npairs = (size_t)BH * T_ * (N_ / 2);
    const int rope_blocks = (int)((npairs + NTH - 1) / NTH);
    rope_kernel<<<rope_blocks, NTH>>>(Q);

    cudaFuncSetAttribute(attn_kernel,
                         cudaFuncAttributeMaxDynamicSharedMemorySize, 64 * 1024);
    attn_kernel<<<NTT * BH, NTH, 64 * 1024>>>(V, O);
}

// round 5
// speedup vs baseline: 1.8825x; 1.7840x over previous
#include <cuda_runtime.h>
#include <cuda_bf16.h>
#include <cstdint>

#define BH   16
#define T_   2048
#define N_   1024
#define D_   128
#define TM   128          // t-rows per CTA tile
#define TSN  128          // s-cols per CTA tile
#define KC   64           // k-chunk (bf16 elems)
#define NCH  16           // N_/KC
#define NTT  16           // T_/TM
#define NTH  256

// ---------------- global scratch (static device alloc — allowed) ----------
__device__ __nv_bfloat16 g_QH[(size_t)BH * T_ * N_];   // 64 MiB
__device__ __nv_bfloat16 g_QL[(size_t)BH * T_ * N_];   // 64 MiB
__device__ __nv_bfloat16 g_VTH[(size_t)BH * D_ * T_];  //  8 MiB (V transposed [d][t])
__device__ __nv_bfloat16 g_VTL[(size_t)BH * D_ * T_];  //  8 MiB

// ---------------- helpers --------------------------------------------------
__device__ __forceinline__ uint32_t smem_u32(const void* p) {
    uint32_t a;
    asm("{ .reg .u64 t; cvta.to.shared.u64 t, %1; cvt.u32.u64 %0, t; }"
        : "=r"(a) : "l"(p));
    return a;
}
__device__ __forceinline__ uint32_t swz(uint32_t off) {   // SW128 swizzle
    return off ^ ((off >> 3) & 0x70);
}
__device__ __forceinline__ void cp16(uint32_t sdst, const void* g) {
    asm volatile("cp.async.cg.shared.global [%0], [%1], 16;\n"
                 :: "r"(sdst), "l"(g) : "memory");
}
#define CP_COMMIT() asm volatile("cp.async.commit_group;\n" ::: "memory")
#define CP_WAIT(n)  asm volatile("cp.async.wait_group %0;\n" :: "n"(n) : "memory")

__device__ __forceinline__ void ldsm4(uint32_t& r0, uint32_t& r1,
                                      uint32_t& r2, uint32_t& r3, uint32_t a) {
    asm volatile("ldmatrix.sync.aligned.m8n8.x4.shared.b16 {%0,%1,%2,%3}, [%4];"
                 : "=r"(r0), "=r"(r1), "=r"(r2), "=r"(r3) : "r"(a));
}
__device__ __forceinline__ void mma_bf16(float c[4],
        uint32_t a0, uint32_t a1, uint32_t a2, uint32_t a3,
        uint32_t b0, uint32_t b1) {
    asm volatile(
        "mma.sync.aligned.m16n8k16.row.col.f32.bf16.bf16.f32 "
        "{%0,%1,%2,%3}, {%4,%5,%6,%7}, {%8,%9}, {%0,%1,%2,%3};"
        : "+f"(c[0]), "+f"(c[1]), "+f"(c[2]), "+f"(c[3])
        : "r"(a0), "r"(a1), "r"(a2), "r"(a3), "r"(b0), "r"(b1));
}
__device__ __forceinline__ void sts32(uint32_t addr, uint32_t v) {
    asm volatile("st.shared.b32 [%0], %1;" :: "r"(addr), "r"(v) : "memory");
}
__device__ __forceinline__ uint32_t pack_bf162(float lo, float hi) {
    __nv_bfloat162 h = __halves2bfloat162(__float2bfloat16(lo), __float2bfloat16(hi));
    return *reinterpret_cast<uint32_t*>(&h);
}

// ---------------- prep 1: RoPE + bf16 hi/lo split -------------------------
__global__ void rope_split_kernel(const float* __restrict__ Q) {
    size_t idx = (size_t)blockIdx.x * blockDim.x + threadIdx.x;  // pair index
    const size_t npairs = (size_t)BH * T_ * (N_ / 2);
    if (idx >= npairs) return;
    int    n2  = (int)(idx % (N_ / 2));
    size_t row = idx / (N_ / 2);
    int    t   = (int)(row % T_);

    float pos  = (float)(2 * n2);
    float freq = exp2f(-16.0f * pos * (1.0f / (float)N_)) * 0.15915494309189535f;
    float r    = (float)t * freq;
    float ph   = (r - floorf(r)) * 6.283185307179586f;
    float s, c;
    __sincosf(ph, &s, &c);

    const float2 q = ((const float2*)Q)[idx];
    float ox = q.x * c - q.y * s;
    float oy = q.y * c + q.x * s;

    __nv_bfloat16 hx = __float2bfloat16(ox);
    __nv_bfloat16 hy = __float2bfloat16(oy);
    __nv_bfloat16 lx = __float2bfloat16(ox - __bfloat162float(hx));
    __nv_bfloat16 ly = __float2bfloat16(oy - __bfloat162float(hy));
    ((__nv_bfloat162*)g_QH)[idx] = __halves2bfloat162(hx, hy);
    ((__nv_bfloat162*)g_QL)[idx] = __halves2bfloat162(lx, ly);
}

// ---------------- prep 2: V transpose + bf16 hi/lo split ------------------
__global__ void vt_split_kernel(const float* __restrict__ V) {
    size_t idx = (size_t)blockIdx.x * blockDim.x + threadIdx.x;  // [bh][d][t]
    const size_t tot = (size_t)BH * D_ * T_;
    if (idx >= tot) return;
    int    t   = (int)(idx % T_);
    size_t r   = idx / T_;
    int    d   = (int)(r % D_);
    size_t bh  = r / D_;
    float v = V[(bh * T_ + t) * D_ + d];
    __nv_bfloat16 h = __float2bfloat16(v);
    g_VTH[idx] = h;
    g_VTL[idx] = __float2bfloat16(v - __bfloat162float(h));
}

// ---------------- attention (mma.sync, bf16x3) ----------------------------
// smem map (bytes):
//   [0, 128K)   : Q chunk double buffer: buf b at b*65536,
//                 tiles within buf: QtH(0) QtL(16K) QsH(32K) QsL(48K)
//                 buf0 region reused for S hi/lo between stages:
//                 SH0(0) SH1(16K) SL0(32K) SL1(48K), each [128][64] bf16
//   [128K,192K) : V tiles: VH0 VH1 VL0 VL1, each [128 d][64 t] bf16
#define SM_V   131072
#define SM_TOT 196608

__device__ __forceinline__ void load_q_chunk(
    uint32_t sb, int buf, int k0, int t0, int s0, int tid,
    const __nv_bfloat16* QHb, const __nv_bfloat16* QLb) {
    int tsel = tid >> 6;        // 0..3: QtH QtL QsH QsL
    int u    = tid & 63;
    int r0   = (tsel < 2) ? t0 : s0;
    const __nv_bfloat16* src = ((tsel & 1) ? QLb : QHb) + (size_t)r0 * N_ + k0;
    uint32_t tb = sb + (uint32_t)buf * 65536u + (uint32_t)tsel * 16384u;
#pragma unroll
    for (int i = 0; i < 16; ++i) {
        int idx = u * 16 + i;              // 0..1023 (16B units)
        int r = idx >> 3, c16 = idx & 7;
        cp16(tb + swz((uint32_t)(r * 128 + c16 * 16)),
             src + (size_t)r * N_ + c16 * 8);
    }
}

__device__ __forceinline__ void load_v_tile(
    uint32_t sb, int s0, int tid,
    const __nv_bfloat16* VHb, const __nv_bfloat16* VLb) {
    int tsel = tid >> 6;        // 0:VH0 1:VH1 2:VL0 3:VL1
    int u    = tid & 63;
    const __nv_bfloat16* src =
        ((tsel < 2) ? VHb : VLb) + (size_t)(s0 + (tsel & 1) * 64);
    uint32_t tb = sb + SM_V + (uint32_t)tsel * 16384u;
#pragma unroll
    for (int i = 0; i < 16; ++i) {
        int idx = u * 16 + i;
        int r = idx >> 3, c16 = idx & 7;
        cp16(tb + swz((uint32_t)(r * 128 + c16 * 16)),
             src + (size_t)r * T_ + c16 * 8);
    }
}

__global__ void __launch_bounds__(NTH, 1)
attn_mma_kernel(float* __restrict__ O) {
    extern __shared__ char smem[];
    uint32_t sb = smem_u32(smem);
    const int tid  = threadIdx.x;
    const int wid  = tid >> 5;
    const int lane = tid & 31;
    const int wm   = wid & 3;         // m (t-row) group: 32 rows
    const int wn   = wid >> 2;        // n group: 64 cols
    const int lrow = lane & 15;       // ldmatrix row-within-16
    const int lgrp = lane >> 4;       // ldmatrix 16B-column select
    const int qr   = lane >> 2;       // C-frag row within 8
    const int qc   = (lane & 3) << 1; // C-frag col pair

    const int bh = blockIdx.x & (BH - 1);
    const int p  = blockIdx.x >> 4;   // 0..7

    const __nv_bfloat16* QHb = g_QH  + (size_t)bh * T_ * N_;
    const __nv_bfloat16* QLb = g_QL  + (size_t)bh * T_ * N_;
    const __nv_bfloat16* VHb = g_VTH + (size_t)bh * D_ * T_;
    const __nv_bfloat16* VLb = g_VTL + (size_t)bh * D_ * T_;
    float* Ob = O + (size_t)bh * T_ * D_;

    for (int rep = 0; rep < 2; ++rep) {
        const int tt = (rep == 0) ? p : (NTT - 1 - p);   // balanced pair: 17 s-tiles
        const int t0 = tt * TM;

        float Oacc[2][8][4];
#pragma unroll
        for (int a = 0; a < 2; ++a)
#pragma unroll
            for (int b = 0; b < 8; ++b)
#pragma unroll
                for (int x = 0; x < 4; ++x) Oacc[a][b][x] = 0.0f;

        for (int st = 0; st <= tt; ++st) {
            const int s0 = st * TSN;

            load_v_tile(sb, s0, tid, VHb, VLb);
            load_q_chunk(sb, 0, 0, t0, s0, tid, QHb, QLb);
            CP_COMMIT();

            float Sacc[2][8][4];
#pragma unroll
            for (int a = 0; a < 2; ++a)
#pragma unroll
                for (int b = 0; b < 8; ++b)
#pragma unroll
                    for (int x = 0; x < 4; ++x) Sacc[a][b][x] = 0.0f;

            // ---- stage 1: S = Qt @ Qs^T, K = 1024, double-buffered chunks ----
            for (int cc = 0; cc < NCH; ++cc) {
                if (cc + 1 < NCH) {
                    load_q_chunk(sb, (cc + 1) & 1, (cc + 1) * KC, t0, s0, tid, QHb, QLb);
                    CP_COMMIT();
                    CP_WAIT(1);
                } else {
                    CP_WAIT(0);
                }
                __syncthreads();

                const uint32_t qb = sb + (uint32_t)(cc & 1) * 65536u;
#pragma unroll
                for (int ks = 0; ks < 4; ++ks) {
                    const int kb = ks * 32 + lgrp * 16;
                    uint32_t aH[2][4], aL[2][4];
#pragma unroll
                    for (int mt = 0; mt < 2; ++mt) {
                        uint32_t ro = (uint32_t)((wm * 32 + mt * 16 + lrow) * 128 + kb);
                        ldsm4(aH[mt][0], aH[mt][1], aH[mt][2], aH[mt][3], qb + swz(ro));
                        ldsm4(aL[mt][0], aL[mt][1], aL[mt][2], aL[mt][3],
                              qb + 16384u + swz(ro));
                    }
#pragma unroll
                    for (int half = 0; half < 2; ++half) {
                        uint32_t bH[4][2], bL[4][2];
#pragma unroll
                        for (int pq = 0; pq < 2; ++pq) {
                            uint32_t ro = (uint32_t)((wn * 64 + half * 32 + pq * 16 + lrow) * 128 + kb);
                            uint32_t r0, r1, r2, r3;
                            ldsm4(r0, r1, r2, r3, qb + 32768u + swz(ro));
                            bH[2 * pq][0] = r0; bH[2 * pq][1] = r2;
                            bH[2 * pq + 1][0] = r1; bH[2 * pq + 1][1] = r3;
                            ldsm4(r0, r1, r2, r3, qb + 49152u + swz(ro));
                            bL[2 * pq][0] = r0; bL[2 * pq][1] = r2;
                            bL[2 * pq + 1][0] = r1; bL[2 * pq + 1][1] = r3;
                        }
#pragma unroll
                        for (int mt = 0; mt < 2; ++mt)
#pragma unroll
                            for (int nt = 0; nt < 4; ++nt) {
                                float* c = Sacc[mt][half * 4 + nt];
                                mma_bf16(c, aH[mt][0], aH[mt][1], aH[mt][2], aH[mt][3],
                                         bH[nt][0], bH[nt][1]);
                                mma_bf16(c, aH[mt][0], aH[mt][1], aH[mt][2], aH[mt][3],
                                         bL[nt][0], bL[nt][1]);
                                mma_bf16(c, aL[mt][0], aL[mt][1], aL[mt][2], aL[mt][3],
                                         bH[nt][0], bH[nt][1]);
                            }
                    }
                }
                __syncthreads();   // chunk cc consumed; buffer reusable 2 iters later
            }

            // ---- mask + bf16 hi/lo split of S into smem (buf0 region) ----
            const bool diag = (st == tt);
#pragma unroll
            for (int mt = 0; mt < 2; ++mt) {
                const int r0 = wm * 32 + mt * 16 + qr;   // tile-local t rows
                const int r1 = r0 + 8;
#pragma unroll
                for (int idx = 0; idx < 8; ++idx) {
                    const int cloc = (idx >> 2) * 32 + (idx & 3) * 8 + qc;  // 0..63
                    const int sg = s0 + wn * 64 + cloc;
                    float c0 = Sacc[mt][idx][0], c1 = Sacc[mt][idx][1];
                    float c2 = Sacc[mt][idx][2], c3 = Sacc[mt][idx][3];
                    if (diag) {
                        if (sg     >= t0 + r0) c0 = 0.0f;
                        if (sg + 1 >= t0 + r0) c1 = 0.0f;
                        if (sg     >= t0 + r1) c2 = 0.0f;
                        if (sg + 1 >= t0 + r1) c3 = 0.0f;
                    }
                    float h0 = __bfloat162float(__float2bfloat16(c0));
                    float h1 = __bfloat162float(__float2bfloat16(c1));
                    float h2 = __bfloat162float(__float2bfloat16(c2));
                    float h3 = __bfloat162float(__float2bfloat16(c3));
                    const uint32_t base = sb + (uint32_t)wn * 16384u;   // ksub = wn
                    const uint32_t o0 = swz((uint32_t)(r0 * 128 + cloc * 2));
                    const uint32_t o1 = swz((uint32_t)(r1 * 128 + cloc * 2));
                    sts32(base + o0,           pack_bf162(h0, h1));
                    sts32(base + o1,           pack_bf162(h2, h3));
                    sts32(base + 32768u + o0,  pack_bf162(c0 - h0, c1 - h1));
                    sts32(base + 32768u + o1,  pack_bf162(c2 - h2, c3 - h3));
                }
            }
            __syncthreads();

            // ---- stage 2: O += Sh@Vh + Sh@Vl + Sl@Vh ----
#pragma unroll
            for (int ks8 = 0; ks8 < 8; ++ks8) {
                const int ksub = ks8 >> 2;
                const int kb   = (ks8 & 3) * 32 + lgrp * 16;
                const uint32_t tS = sb + (uint32_t)ksub * 16384u;
                const uint32_t tV = sb + SM_V + (uint32_t)ksub * 16384u;
                uint32_t aH[2][4], aL[2][4];
#pragma unroll
                for (int mt = 0; mt < 2; ++mt) {
                    uint32_t ro = (uint32_t)((wm * 32 + mt * 16 + lrow) * 128 + kb);
                    ldsm4(aH[mt][0], aH[mt][1], aH[mt][2], aH[mt][3], tS + swz(ro));
                    ldsm4(aL[mt][0], aL[mt][1], aL[mt][2], aL[mt][3],
                          tS + 32768u + swz(ro));
                }
#pragma unroll
                for (int half = 0; half < 2; ++half) {
                    uint32_t bH[4][2], bL[4][2];
#pragma unroll
                    for (int pq = 0; pq < 2; ++pq) {
                        uint32_t ro = (uint32_t)((wn * 64 + half * 32 + pq * 16 + lrow) * 128 + kb);
                        uint32_t r0, r1, r2, r3;
                        ldsm4(r0, r1, r2, r3, tV + swz(ro));
                        bH[2 * pq][0] = r0; bH[2 * pq][1] = r2;
                        bH[2 * pq + 1][0] = r1; bH[2 * pq + 1][1] = r3;
                        ldsm4(r0, r1, r2, r3, tV + 32768u + swz(ro));
                        bL[2 * pq][0] = r0; bL[2 * pq][1] = r2;
                        bL[2 * pq + 1][0] = r1; bL[2 * pq + 1][1] = r3;
                    }
#pragma unroll
                    for (int mt = 0; mt < 2; ++mt)
#pragma unroll
                        for (int nt = 0; nt < 4; ++nt) {
                            float* c = Oacc[mt][half * 4 + nt];
                            mma_bf16(c, aH[mt][0], aH[mt][1], aH[mt][2], aH[mt][3],
                                     bH[nt][0], bH[nt][1]);
                            mma_bf16(c, aH[mt][0], aH[mt][1], aH[mt][2], aH[mt][3],
                                     bL[nt][0], bL[nt][1]);
                            mma_bf16(c, aL[mt][0], aL[mt][1], aL[mt][2], aL[mt][3],
                                     bH[nt][0], bH[nt][1]);
                        }
                }
            }
            __syncthreads();   // S/V smem consumed before next s-tile overwrites
        }

        // ---- O writeback for this t-tile ----
#pragma unroll
        for (int mt = 0; mt < 2; ++mt) {
            const int r0 = t0 + wm * 32 + mt * 16 + qr;
            const int r1 = r0 + 8;
#pragma unroll
            for (int idx = 0; idx < 8; ++idx) {
                const int d = wn * 64 + (idx >> 2) * 32 + (idx & 3) * 8 + qc;
                *(float2*)(Ob + (size_t)r0 * D_ + d) =
                    make_float2(Oacc[mt][idx][0], Oacc[mt][idx][1]);
                *(float2*)(Ob + (size_t)r1 * D_ + d) =
                    make_float2(Oacc[mt][idx][2], Oacc[mt][idx][3]);
            }
        }
    }
}

// ---------------------------------------------------------------------------
extern "C" void kernel_launch(void* const* d_in, const int* in_sizes, int n_in,
                              void* d_out, int out_size) {
    const float* Q = (const float*)d_in[0];
    const float* V = (const float*)d_in[2];   // d_in[1] is K == Q
    float* O = (float*)d_out;

    const size_t npairs = (size_t)BH * T_ * (N_ / 2);
    rope_split_kernel<<<(int)((npairs + NTH - 1) / NTH), NTH>>>(Q);

    const size_t nvt = (size_t)BH * D_ * T_;
    vt_split_kernel<<<(int)((nvt + NTH - 1) / NTH), NTH>>>(V);

    cudaFuncSetAttribute(attn_mma_kernel,
                         cudaFuncAttributeMaxDynamicSharedMemorySize, SM_TOT);
    attn_mma_kernel<<<8 * BH, NTH, SM_TOT>>>(O);
}

// round 6
// speedup vs baseline: 1.8836x; 1.0006x over previous
#include <cuda_runtime.h>
#include <cuda_bf16.h>
#include <cstdint>

#define BH   16
#define T_   2048
#define N_   1024
#define D_   128
#define TM   128          // t-rows per CTA tile
#define TSN  128          // s-cols per CTA tile
#define KC   64           // k-chunk (bf16 elems)
#define NCH  16           // N_/KC
#define NTT  16           // T_/TM
#define NTH  256

// ---------------- global scratch (static device alloc — allowed) ----------
__device__ __nv_bfloat16 g_QH[(size_t)BH * T_ * N_];   // 64 MiB
__device__ __nv_bfloat16 g_QL[(size_t)BH * T_ * N_];   // 64 MiB
__device__ __nv_bfloat16 g_VTH[(size_t)BH * D_ * T_];  //  8 MiB (V transposed [d][t])
__device__ __nv_bfloat16 g_VTL[(size_t)BH * D_ * T_];  //  8 MiB

// ---------------- helpers --------------------------------------------------
__device__ __forceinline__ uint32_t smem_u32(const void* p) {
    uint32_t a;
    asm("{ .reg .u64 t; cvta.to.shared.u64 t, %1; cvt.u32.u64 %0, t; }"
        : "=r"(a) : "l"(p));
    return a;
}
__device__ __forceinline__ uint32_t swz(uint32_t off) {   // SW128 swizzle
    return off ^ ((off >> 3) & 0x70);
}
__device__ __forceinline__ void cp16(uint32_t sdst, const void* g) {
    asm volatile("cp.async.cg.shared.global [%0], [%1], 16;\n"
                 :: "r"(sdst), "l"(g) : "memory");
}
#define CP_COMMIT() asm volatile("cp.async.commit_group;\n" ::: "memory")
#define CP_WAIT(n)  asm volatile("cp.async.wait_group %0;\n" :: "n"(n) : "memory")

__device__ __forceinline__ void ldsm4(uint32_t& r0, uint32_t& r1,
                                      uint32_t& r2, uint32_t& r3, uint32_t a) {
    asm volatile("ldmatrix.sync.aligned.m8n8.x4.shared.b16 {%0,%1,%2,%3}, [%4];"
                 : "=r"(r0), "=r"(r1), "=r"(r2), "=r"(r3) : "r"(a));
}
__device__ __forceinline__ void mma_bf16(float c[4],
        uint32_t a0, uint32_t a1, uint32_t a2, uint32_t a3,
        uint32_t b0, uint32_t b1) {
    asm volatile(
        "mma.sync.aligned.m16n8k16.row.col.f32.bf16.bf16.f32 "
        "{%0,%1,%2,%3}, {%4,%5,%6,%7}, {%8,%9}, {%0,%1,%2,%3};"
        : "+f"(c[0]), "+f"(c[1]), "+f"(c[2]), "+f"(c[3])
        : "r"(a0), "r"(a1), "r"(a2), "r"(a3), "r"(b0), "r"(b1));
}
__device__ __forceinline__ void sts32(uint32_t addr, uint32_t v) {
    asm volatile("st.shared.b32 [%0], %1;" :: "r"(addr), "r"(v) : "memory");
}
__device__ __forceinline__ uint32_t pack_bf162(float lo, float hi) {
    __nv_bfloat162 h = __halves2bfloat162(__float2bfloat16(lo), __float2bfloat16(hi));
    return *reinterpret_cast<uint32_t*>(&h);
}

// ---------------- prep 1: RoPE + bf16 hi/lo split -------------------------
__global__ void rope_split_kernel(const float* __restrict__ Q) {
    size_t idx = (size_t)blockIdx.x * blockDim.x + threadIdx.x;  // pair index
    const size_t npairs = (size_t)BH * T_ * (N_ / 2);
    if (idx >= npairs) return;
    int    n2  = (int)(idx % (N_ / 2));
    size_t row = idx / (N_ / 2);
    int    t   = (int)(row % T_);

    float pos  = (float)(2 * n2);
    float freq = exp2f(-16.0f * pos * (1.0f / (float)N_)) * 0.15915494309189535f;
    float r    = (float)t * freq;
    float ph   = (r - floorf(r)) * 6.283185307179586f;
    float s, c;
    __sincosf(ph, &s, &c);

    const float2 q = ((const float2*)Q)[idx];
    float ox = q.x * c - q.y * s;
    float oy = q.y * c + q.x * s;

    __nv_bfloat16 hx = __float2bfloat16(ox);
    __nv_bfloat16 hy = __float2bfloat16(oy);
    __nv_bfloat16 lx = __float2bfloat16(ox - __bfloat162float(hx));
    __nv_bfloat16 ly = __float2bfloat16(oy - __bfloat162float(hy));
    ((__nv_bfloat162*)g_QH)[idx] = __halves2bfloat162(hx, hy);
    ((__nv_bfloat162*)g_QL)[idx] = __halves2bfloat162(lx, ly);
}

// ---------------- prep 2: V transpose + bf16 hi/lo split ------------------
__global__ void vt_split_kernel(const float* __restrict__ V) {
    size_t idx = (size_t)blockIdx.x * blockDim.x + threadIdx.x;  // [bh][d][t]
    const size_t tot = (size_t)BH * D_ * T_;
    if (idx >= tot) return;
    int    t   = (int)(idx % T_);
    size_t r   = idx / T_;
    int    d   = (int)(r % D_);
    size_t bh  = r / D_;
    float v = V[(bh * T_ + t) * D_ + d];
    __nv_bfloat16 h = __float2bfloat16(v);
    g_VTH[idx] = h;
    g_VTL[idx] = __float2bfloat16(v - __bfloat162float(h));
}

// ---------------- attention (mma.sync, bf16x3) ----------------------------
// smem map (bytes):
//   [0, 128K)   : Q chunk double buffer: buf b at b*65536,
//                 tiles within buf: QtH(0) QtL(16K) QsH(32K) QsL(48K)
//                 buf0 region reused for S hi/lo between stages:
//                 SH0(0) SH1(16K) SL0(32K) SL1(48K), each [128][64] bf16
//   [128K,192K) : V tiles: VH0 VH1 VL0 VL1, each [128 d][64 t] bf16
#define SM_V   131072
#define SM_TOT 196608

__device__ __forceinline__ void load_q_chunk(
    uint32_t sb, int buf, int k0, int t0, int s0, int tid,
    const __nv_bfloat16* QHb, const __nv_bfloat16* QLb) {
    int tsel = tid >> 6;        // 0..3: QtH QtL QsH QsL
    int u    = tid & 63;
    int r0   = (tsel < 2) ? t0 : s0;
    const __nv_bfloat16* src = ((tsel & 1) ? QLb : QHb) + (size_t)r0 * N_ + k0;
    uint32_t tb = sb + (uint32_t)buf * 65536u + (uint32_t)tsel * 16384u;
#pragma unroll
    for (int i = 0; i < 16; ++i) {
        int idx = u * 16 + i;              // 0..1023 (16B units)
        int r = idx >> 3, c16 = idx & 7;
        cp16(tb + swz((uint32_t)(r * 128 + c16 * 16)),
             src + (size_t)r * N_ + c16 * 8);
    }
}

__device__ __forceinline__ void load_v_tile(
    uint32_t sb, int s0, int tid,
    const __nv_bfloat16* VHb, const __nv_bfloat16* VLb) {
    int tsel = tid >> 6;        // 0:VH0 1:VH1 2:VL0 3:VL1
    int u    = tid & 63;
    const __nv_bfloat16* src =
        ((tsel < 2) ? VHb : VLb) + (size_t)(s0 + (tsel & 1) * 64);
    uint32_t tb = sb + SM_V + (uint32_t)tsel * 16384u;
#pragma unroll
    for (int i = 0; i < 16; ++i) {
        int idx = u * 16 + i;
        int r = idx >> 3, c16 = idx & 7;
        cp16(tb + swz((uint32_t)(r * 128 + c16 * 16)),
             src + (size_t)r * T_ + c16 * 8);
    }
}

__global__ void __launch_bounds__(NTH, 1)
attn_mma_kernel(float* __restrict__ O) {
    extern __shared__ char smem[];
    uint32_t sb = smem_u32(smem);
    const int tid  = threadIdx.x;
    const int wid  = tid >> 5;
    const int lane = tid & 31;
    const int wm   = wid & 3;         // m (t-row) group: 32 rows
    const int wn   = wid >> 2;        // n group: 64 cols
    const int lrow = lane & 15;       // ldmatrix row-within-16
    const int lgrp = lane >> 4;       // ldmatrix 16B-column select
    const int qr   = lane >> 2;       // C-frag row within 8
    const int qc   = (lane & 3) << 1; // C-frag col pair

    const int bh = blockIdx.x & (BH - 1);
    const int p  = blockIdx.x >> 4;   // 0..7

    const __nv_bfloat16* QHb = g_QH  + (size_t)bh * T_ * N_;
    const __nv_bfloat16* QLb = g_QL  + (size_t)bh * T_ * N_;
    const __nv_bfloat16* VHb = g_VTH + (size_t)bh * D_ * T_;
    const __nv_bfloat16* VLb = g_VTL + (size_t)bh * D_ * T_;
    float* Ob = O + (size_t)bh * T_ * D_;

    for (int rep = 0; rep < 2; ++rep) {
        const int tt = (rep == 0) ? p : (NTT - 1 - p);   // balanced pair: 17 s-tiles
        const int t0 = tt * TM;

        float Oacc[2][8][4];
#pragma unroll
        for (int a = 0; a < 2; ++a)
#pragma unroll
            for (int b = 0; b < 8; ++b)
#pragma unroll
                for (int x = 0; x < 4; ++x) Oacc[a][b][x] = 0.0f;

        for (int st = 0; st <= tt; ++st) {
            const int s0 = st * TSN;

            load_v_tile(sb, s0, tid, VHb, VLb);
            load_q_chunk(sb, 0, 0, t0, s0, tid, QHb, QLb);
            CP_COMMIT();

            float Sacc[2][8][4];
#pragma unroll
            for (int a = 0; a < 2; ++a)
#pragma unroll
                for (int b = 0; b < 8; ++b)
#pragma unroll
                    for (int x = 0; x < 4; ++x) Sacc[a][b][x] = 0.0f;

            // ---- stage 1: S = Qt @ Qs^T, K = 1024, double-buffered chunks ----
            for (int cc = 0; cc < NCH; ++cc) {
                if (cc + 1 < NCH) {
                    load_q_chunk(sb, (cc + 1) & 1, (cc + 1) * KC, t0, s0, tid, QHb, QLb);
                    CP_COMMIT();
                    CP_WAIT(1);
                } else {
                    CP_WAIT(0);
                }
                __syncthreads();

                const uint32_t qb = sb + (uint32_t)(cc & 1) * 65536u;
#pragma unroll
                for (int ks = 0; ks < 4; ++ks) {
                    const int kb = ks * 32 + lgrp * 16;
                    uint32_t aH[2][4], aL[2][4];
#pragma unroll
                    for (int mt = 0; mt < 2; ++mt) {
                        uint32_t ro = (uint32_t)((wm * 32 + mt * 16 + lrow) * 128 + kb);
                        ldsm4(aH[mt][0], aH[mt][1], aH[mt][2], aH[mt][3], qb + swz(ro));
                        ldsm4(aL[mt][0], aL[mt][1], aL[mt][2], aL[mt][3],
                              qb + 16384u + swz(ro));
                    }
#pragma unroll
                    for (int half = 0; half < 2; ++half) {
                        uint32_t bH[4][2], bL[4][2];
#pragma unroll
                        for (int pq = 0; pq < 2; ++pq) {
                            uint32_t ro = (uint32_t)((wn * 64 + half * 32 + pq * 16 + lrow) * 128 + kb);
                            uint32_t r0, r1, r2, r3;
                            ldsm4(r0, r1, r2, r3, qb + 32768u + swz(ro));
                            bH[2 * pq][0] = r0; bH[2 * pq][1] = r2;
                            bH[2 * pq + 1][0] = r1; bH[2 * pq + 1][1] = r3;
                            ldsm4(r0, r1, r2, r3, qb + 49152u + swz(ro));
                            bL[2 * pq][0] = r0; bL[2 * pq][1] = r2;
                            bL[2 * pq + 1][0] = r1; bL[2 * pq + 1][1] = r3;
                        }
#pragma unroll
                        for (int mt = 0; mt < 2; ++mt)
#pragma unroll
                            for (int nt = 0; nt < 4; ++nt) {
                                float* c = Sacc[mt][half * 4 + nt];
                                mma_bf16(c, aH[mt][0], aH[mt][1], aH[mt][2], aH[mt][3],
                                         bH[nt][0], bH[nt][1]);
                                mma_bf16(c, aH[mt][0], aH[mt][1], aH[mt][2], aH[mt][3],
                                         bL[nt][0], bL[nt][1]);
                                mma_bf16(c, aL[mt][0], aL[mt][1], aL[mt][2], aL[mt][3],
                                         bH[nt][0], bH[nt][1]);
                            }
                    }
                }
                __syncthreads();   // chunk cc consumed; buffer reusable 2 iters later
            }

            // ---- mask + bf16 hi/lo split of S into smem (buf0 region) ----
            const bool diag = (st == tt);
#pragma unroll
            for (int mt = 0; mt < 2; ++mt) {
                const int r0 = wm * 32 + mt * 16 + qr;   // tile-local t rows
                const int r1 = r0 + 8;
#pragma unroll
                for (int idx = 0; idx < 8; ++idx) {
                    const int cloc = (idx >> 2) * 32 + (idx & 3) * 8 + qc;  // 0..63
                    const int sg = s0 + wn * 64 + cloc;
                    float c0 = Sacc[mt][idx][0], c1 = Sacc[mt][idx][1];
                    float c2 = Sacc[mt][idx][2], c3 = Sacc[mt][idx][3];
                    if (diag) {
                        if (sg     >= t0 + r0) c0 = 0.0f;
                        if (sg + 1 >= t0 + r0) c1 = 0.0f;
                        if (sg     >= t0 + r1) c2 = 0.0f;
                        if (sg + 1 >= t0 + r1) c3 = 0.0f;
                    }
                    float h0 = __bfloat162float(__float2bfloat16(c0));
                    float h1 = __bfloat162float(__float2bfloat16(c1));
                    float h2 = __bfloat162float(__float2bfloat16(c2));
                    float h3 = __bfloat162float(__float2bfloat16(c3));
                    const uint32_t base = sb + (uint32_t)wn * 16384u;   // ksub = wn
                    const uint32_t o0 = swz((uint32_t)(r0 * 128 + cloc * 2));
                    const uint32_t o1 = swz((uint32_t)(r1 * 128 + cloc * 2));
                    sts32(base + o0,           pack_bf162(h0, h1));
                    sts32(base + o1,           pack_bf162(h2, h3));
                    sts32(base + 32768u + o0,  pack_bf162(c0 - h0, c1 - h1));
                    sts32(base + 32768u + o1,  pack_bf162(c2 - h2, c3 - h3));
                }
            }
            __syncthreads();

            // ---- stage 2: O += Sh@Vh + Sh@Vl + Sl@Vh ----
#pragma unroll
            for (int ks8 = 0; ks8 < 8; ++ks8) {
                const int ksub = ks8 >> 2;
                const int kb   = (ks8 & 3) * 32 + lgrp * 16;
                const uint32_t tS = sb + (uint32_t)ksub * 16384u;
                const uint32_t tV = sb + SM_V + (uint32_t)ksub * 16384u;
                uint32_t aH[2][4], aL[2][4];
#pragma unroll
                for (int mt = 0; mt < 2; ++mt) {
                    uint32_t ro = (uint32_t)((wm * 32 + mt * 16 + lrow) * 128 + kb);
                    ldsm4(aH[mt][0], aH[mt][1], aH[mt][2], aH[mt][3], tS + swz(ro));
                    ldsm4(aL[mt][0], aL[mt][1], aL[mt][2], aL[mt][3],
                          tS + 32768u + swz(ro));
                }
#pragma unroll
                for (int half = 0; half < 2; ++half) {
                    uint32_t bH[4][2], bL[4][2];
#pragma unroll
                    for (int pq = 0; pq < 2; ++pq) {
                        uint32_t ro = (uint32_t)((wn * 64 + half * 32 + pq * 16 + lrow) * 128 + kb);
                        uint32_t r0, r1, r2, r3;
                        ldsm4(r0, r1, r2, r3, tV + swz(ro));
                        bH[2 * pq][0] = r0; bH[2 * pq][1] = r2;
                        bH[2 * pq + 1][0] = r1; bH[2 * pq + 1][1] = r3;
                        ldsm4(r0, r1, r2, r3, tV + 32768u + swz(ro));
                        bL[2 * pq][0] = r0; bL[2 * pq][1] = r2;
                        bL[2 * pq + 1][0] = r1; bL[2 * pq + 1][1] = r3;
                    }
#pragma unroll
                    for (int mt = 0; mt < 2; ++mt)
#pragma unroll
                        for (int nt = 0; nt < 4; ++nt) {
                            float* c = Oacc[mt][half * 4 + nt];
                            mma_bf16(c, aH[mt][0], aH[mt][1], aH[mt][2], aH[mt][3],
                                     bH[nt][0], bH[nt][1]);
                            mma_bf16(c, aH[mt][0], aH[mt][1], aH[mt][2], aH[mt][3],
                                     bL[nt][0], bL[nt][1]);
                            mma_bf16(c, aL[mt][0], aL[mt][1], aL[mt][2], aL[mt][3],
                                     bH[nt][0], bH[nt][1]);
                        }
                }
            }
            __syncthreads();   // S/V smem consumed before next s-tile overwrites
        }

        // ---- O writeback for this t-tile ----
#pragma unroll
        for (int mt = 0; mt < 2; ++mt) {
            const int r0 = t0 + wm * 32 + mt * 16 + qr;
            const int r1 = r0 + 8;
#pragma unroll
            for (int idx = 0; idx < 8; ++idx) {
                const int d = wn * 64 + (idx >> 2) * 32 + (idx & 3) * 8 + qc;
                *(float2*)(Ob + (size_t)r0 * D_ + d) =
                    make_float2(Oacc[mt][idx][0], Oacc[mt][idx][1]);
                *(float2*)(Ob + (size_t)r1 * D_ + d) =
                    make_float2(Oacc[mt][idx][2], Oacc[mt][idx][3]);
            }
        }
    }
}

// ---------------------------------------------------------------------------
extern "C" void kernel_launch(void* const* d_in, const int* in_sizes, int n_in,
                              void* d_out, int out_size) {
    const float* Q = (const float*)d_in[0];
    const float* V = (const float*)d_in[2];   // d_in[1] is K == Q
    float* O = (float*)d_out;

    const size_t npairs = (size_t)BH * T_ * (N_ / 2);
    rope_split_kernel<<<(int)((npairs + NTH - 1) / NTH), NTH>>>(Q);

    const size_t nvt = (size_t)BH * D_ * T_;
    vt_split_kernel<<<(int)((nvt + NTH - 1) / NTH), NTH>>>(V);

    cudaFuncSetAttribute(attn_mma_kernel,
                         cudaFuncAttributeMaxDynamicSharedMemorySize, SM_TOT);
    attn_mma_kernel<<<8 * BH, NTH, SM_TOT>>>(O);
}

// round 7
// speedup vs baseline: 2.3421x; 1.2435x over previous
#include <cuda_runtime.h>
#include <cuda_fp16.h>
#include <cstdint>

#define BH   16
#define T_   2048
#define N_   1024
#define D_   128
#define TM   128          // t-rows per CTA tile
#define TSN  128          // s-cols per CTA tile
#define KC   64           // k-chunk (fp16 elems)
#define NCH  16           // N_/KC
#define NTT  16           // T_/TM
#define NTH  256

// ---------------- global scratch (static device alloc — allowed) ----------
__device__ __half g_QH[(size_t)BH * T_ * N_];   // 64 MiB
__device__ __half g_QL[(size_t)BH * T_ * N_];   // 64 MiB
__device__ __half g_VTH[(size_t)BH * D_ * T_];  //  8 MiB (V transposed [d][t])
__device__ __half g_VTL[(size_t)BH * D_ * T_];  //  8 MiB

// ---------------- helpers --------------------------------------------------
__device__ __forceinline__ uint32_t smem_u32(const void* p) {
    uint32_t a;
    asm("{ .reg .u64 t; cvta.to.shared.u64 t, %1; cvt.u32.u64 %0, t; }"
        : "=r"(a) : "l"(p));
    return a;
}
__device__ __forceinline__ uint32_t swz(uint32_t off) {   // SW128 swizzle
    return off ^ ((off >> 3) & 0x70);
}
__device__ __forceinline__ void cp16(uint32_t sdst, const void* g) {
    asm volatile("cp.async.cg.shared.global [%0], [%1], 16;\n"
                 :: "r"(sdst), "l"(g) : "memory");
}
#define CP_COMMIT() asm volatile("cp.async.commit_group;\n" ::: "memory")
#define CP_WAIT1()  asm volatile("cp.async.wait_group 1;\n" ::: "memory")
#define CP_WAIT2()  asm volatile("cp.async.wait_group 2;\n" ::: "memory")

__device__ __forceinline__ void ldsm4(uint32_t& r0, uint32_t& r1,
                                      uint32_t& r2, uint32_t& r3, uint32_t a) {
    asm volatile("ldmatrix.sync.aligned.m8n8.x4.shared.b16 {%0,%1,%2,%3}, [%4];"
                 : "=r"(r0), "=r"(r1), "=r"(r2), "=r"(r3) : "r"(a));
}
__device__ __forceinline__ void mma_fp16(float c[4],
        uint32_t a0, uint32_t a1, uint32_t a2, uint32_t a3,
        uint32_t b0, uint32_t b1) {
    asm volatile(
        "mma.sync.aligned.m16n8k16.row.col.f32.f16.f16.f32 "
        "{%0,%1,%2,%3}, {%4,%5,%6,%7}, {%8,%9}, {%0,%1,%2,%3};"
        : "+f"(c[0]), "+f"(c[1]), "+f"(c[2]), "+f"(c[3])
        : "r"(a0), "r"(a1), "r"(a2), "r"(a3), "r"(b0), "r"(b1));
}
__device__ __forceinline__ void sts32(uint32_t addr, uint32_t v) {
    asm volatile("st.shared.b32 [%0], %1;" :: "r"(addr), "r"(v) : "memory");
}
__device__ __forceinline__ uint32_t pack_h2(float lo, float hi) {
    __half2 h = __floats2half2_rn(lo, hi);
    return *reinterpret_cast<uint32_t*>(&h);
}

// ---------------- prep 1: RoPE + fp16 hi/lo split -------------------------
__global__ void rope_split_kernel(const float* __restrict__ Q) {
    size_t idx = (size_t)blockIdx.x * blockDim.x + threadIdx.x;  // pair index
    const size_t npairs = (size_t)BH * T_ * (N_ / 2);
    if (idx >= npairs) return;
    int    n2  = (int)(idx % (N_ / 2));
    size_t row = idx / (N_ / 2);
    int    t   = (int)(row % T_);

    float pos  = (float)(2 * n2);
    float freq = exp2f(-16.0f * pos * (1.0f / (float)N_)) * 0.15915494309189535f;
    float r    = (float)t * freq;
    float ph   = (r - floorf(r)) * 6.283185307179586f;
    float s, c;
    __sincosf(ph, &s, &c);

    const float2 q = ((const float2*)Q)[idx];
    float ox = q.x * c - q.y * s;
    float oy = q.y * c + q.x * s;

    __half hx = __float2half(ox);
    __half hy = __float2half(oy);
    __half lx = __float2half(ox - __half2float(hx));
    __half ly = __float2half(oy - __half2float(hy));
    ((__half2*)g_QH)[idx] = __halves2half2(hx, hy);
    ((__half2*)g_QL)[idx] = __halves2half2(lx, ly);
}

// ---------------- prep 2: V transpose + fp16 hi/lo split ------------------
__global__ void vt_split_kernel(const float* __restrict__ V) {
    size_t idx = (size_t)blockIdx.x * blockDim.x + threadIdx.x;  // [bh][d][t]
    const size_t tot = (size_t)BH * D_ * T_;
    if (idx >= tot) return;
    int    t   = (int)(idx % T_);
    size_t r   = idx / T_;
    int    d   = (int)(r % D_);
    size_t bh  = r / D_;
    float v = V[(bh * T_ + t) * D_ + d];
    __half h = __float2half(v);
    g_VTH[idx] = h;
    g_VTL[idx] = __float2half(v - __half2float(h));
}

// ---------------- attention (mma.sync fp16, 2-product stage1) -------------
// smem map (bytes):
//   [0, 96K)     : Q chunk double buffer, buf b at b*49152:
//                  QtH(+0) QsH(+16K) QsL(+32K), each [128 rows][64 k] fp16
//   [96K, 160K)  : V tiles: VH0 VH1 VL0 VL1, each [128 d][64 t] fp16
//   [160K, 224K) : S tiles: SH0 SH1 SL0 SL1, each [128 t][64 s] fp16
#define SM_V   98304
#define SM_S   163840
#define SM_TOT 229376

__device__ __forceinline__ void load_q_chunk(
    uint32_t sb, int buf, int k0, int t0, int s0, int tid,
    const __half* QHb, const __half* QLb) {
    int tsel = tid >> 6;        // 0: QtH, 1: QsH, 2: QsL, 3: idle
    if (tsel == 3) return;
    int u = tid & 63;
    const __half* src;
    if (tsel == 0)      src = QHb + (size_t)t0 * N_ + k0;
    else if (tsel == 1) src = QHb + (size_t)s0 * N_ + k0;
    else                src = QLb + (size_t)s0 * N_ + k0;
    uint32_t tb = sb + (uint32_t)buf * 49152u + (uint32_t)tsel * 16384u;
#pragma unroll
    for (int i = 0; i < 16; ++i) {
        int idx = u * 16 + i;              // 0..1023 (16B units)
        int r = idx >> 3, c16 = idx & 7;
        cp16(tb + swz((uint32_t)(r * 128 + c16 * 16)),
             src + (size_t)r * N_ + c16 * 8);
    }
}

__device__ __forceinline__ void load_v_tile(
    uint32_t sb, int s0, int tid,
    const __half* VHb, const __half* VLb) {
    int tsel = tid >> 6;        // 0:VH0 1:VH1 2:VL0 3:VL1
    int u    = tid & 63;
    const __half* src =
        ((tsel < 2) ? VHb : VLb) + (size_t)(s0 + (tsel & 1) * 64);
    uint32_t tb = sb + SM_V + (uint32_t)tsel * 16384u;
#pragma unroll
    for (int i = 0; i < 16; ++i) {
        int idx = u * 16 + i;
        int r = idx >> 3, c16 = idx & 7;
        cp16(tb + swz((uint32_t)(r * 128 + c16 * 16)),
             src + (size_t)r * T_ + c16 * 8);
    }
}

__global__ void __launch_bounds__(NTH, 1)
attn_mma_kernel(float* __restrict__ O) {
    extern __shared__ char smem[];
    uint32_t sb = smem_u32(smem);
    const int tid  = threadIdx.x;
    const int wid  = tid >> 5;
    const int lane = tid & 31;
    const int wm   = wid & 3;         // m (t-row) group: 32 rows
    const int wn   = wid >> 2;        // n group: 64 cols
    const int lrow = lane & 15;       // ldmatrix row-within-16
    const int lgrp = lane >> 4;       // ldmatrix 16B-column select
    const int qr   = lane >> 2;       // C-frag row within 8
    const int qc   = (lane & 3) << 1; // C-frag col pair

    const int bh = blockIdx.x / 9;
    const int c  = blockIdx.x % 9;

    int tts[2]; int nrep;
    if (c == 0)      { tts[0] = 15; tts[1] = 15; nrep = 1; }
    else if (c == 8) { tts[0] = 7;  tts[1] = 7;  nrep = 1; }
    else             { tts[0] = 15 - c; tts[1] = c - 1; nrep = 2; }

    const __half* QHb = g_QH  + (size_t)bh * T_ * N_;
    const __half* QLb = g_QL  + (size_t)bh * T_ * N_;
    const __half* VHb = g_VTH + (size_t)bh * D_ * T_;
    const __half* VLb = g_VTL + (size_t)bh * D_ * T_;
    float* Ob = O + (size_t)bh * T_ * D_;

    // prologue: first chunk of first s-tile into buf0
    load_q_chunk(sb, 0, 0, tts[0] * TM, 0, tid, QHb, QLb);
    CP_COMMIT();

    for (int rep = 0; rep < nrep; ++rep) {
        const int tt = tts[rep];
        const int t0 = tt * TM;

        float Oacc[2][8][4];
#pragma unroll
        for (int a = 0; a < 2; ++a)
#pragma unroll
            for (int b = 0; b < 8; ++b)
#pragma unroll
                for (int x = 0; x < 4; ++x) Oacc[a][b][x] = 0.0f;

        for (int st = 0; st <= tt; ++st) {
            const int s0 = st * TSN;
            const bool diag = (st == tt);
            const bool wskip = diag && (wn * 64 >= wm * 32 + 32);

            load_v_tile(sb, s0, tid, VHb, VLb);
            CP_COMMIT();

            float Sacc[2][8][4];
#pragma unroll
            for (int a = 0; a < 2; ++a)
#pragma unroll
                for (int b = 0; b < 8; ++b)
#pragma unroll
                    for (int x = 0; x < 4; ++x) Sacc[a][b][x] = 0.0f;

            // ---- stage 1: S = QtH @ (QsH + QsL)^T, 16 double-buffered chunks
            for (int cc = 0; cc < NCH; ++cc) {
                if (cc + 1 < NCH) {
                    load_q_chunk(sb, (cc + 1) & 1, (cc + 1) * KC, t0, s0, tid,
                                 QHb, QLb);
                } else if (st < tt) {           // prefetch next s-tile chunk0
                    load_q_chunk(sb, 0, 0, t0, s0 + TSN, tid, QHb, QLb);
                } else if (rep + 1 < nrep) {    // prefetch next t-tile chunk0
                    load_q_chunk(sb, 0, 0, tts[rep + 1] * TM, 0, tid, QHb, QLb);
                }
                CP_COMMIT();
                if (cc == 0) { CP_WAIT2(); } else { CP_WAIT1(); }
                __syncthreads();

                if (!wskip) {
                    const uint32_t qb = sb + (uint32_t)(cc & 1) * 49152u;
#pragma unroll
                    for (int ks = 0; ks < 4; ++ks) {
                        const int kb = ks * 32 + lgrp * 16;
                        uint32_t aH[2][4];
#pragma unroll
                        for (int mt = 0; mt < 2; ++mt) {
                            uint32_t ro = (uint32_t)((wm * 32 + mt * 16 + lrow) * 128 + kb);
                            ldsm4(aH[mt][0], aH[mt][1], aH[mt][2], aH[mt][3],
                                  qb + swz(ro));
                        }
#pragma unroll
                        for (int half = 0; half < 2; ++half) {
                            if (diag && (wn * 64 + half * 32 >= wm * 32 + 32)) continue;
                            uint32_t bH[4][2], bL[4][2];
#pragma unroll
                            for (int pq = 0; pq < 2; ++pq) {
                                uint32_t ro = (uint32_t)((wn * 64 + half * 32 + pq * 16 + lrow) * 128 + kb);
                                uint32_t r0, r1, r2, r3;
                                ldsm4(r0, r1, r2, r3, qb + 16384u + swz(ro));
                                bH[2 * pq][0] = r0; bH[2 * pq][1] = r2;
                                bH[2 * pq + 1][0] = r1; bH[2 * pq + 1][1] = r3;
                                ldsm4(r0, r1, r2, r3, qb + 32768u + swz(ro));
                                bL[2 * pq][0] = r0; bL[2 * pq][1] = r2;
                                bL[2 * pq + 1][0] = r1; bL[2 * pq + 1][1] = r3;
                            }
#pragma unroll
                            for (int mt = 0; mt < 2; ++mt)
#pragma unroll
                                for (int nt = 0; nt < 4; ++nt) {
                                    if (diag && (wn * 64 + half * 32 + nt * 8 >=
                                                 wm * 32 + mt * 16 + 16)) continue;
                                    float* cp = Sacc[mt][half * 4 + nt];
                                    mma_fp16(cp, aH[mt][0], aH[mt][1], aH[mt][2],
                                             aH[mt][3], bH[nt][0], bH[nt][1]);
                                    mma_fp16(cp, aH[mt][0], aH[mt][1], aH[mt][2],
                                             aH[mt][3], bL[nt][0], bL[nt][1]);
                                }
                        }
                    }
                }
                __syncthreads();
            }

            // ---- mask + fp16 hi/lo split of S into smem ----
#pragma unroll
            for (int mt = 0; mt < 2; ++mt) {
                const int r0 = wm * 32 + mt * 16 + qr;   // tile-local t rows
                const int r1 = r0 + 8;
#pragma unroll
                for (int idx = 0; idx < 8; ++idx) {
                    const int cloc = (idx >> 2) * 32 + (idx & 3) * 8 + qc;  // 0..63
                    const int sg = s0 + wn * 64 + cloc;
                    float c0 = Sacc[mt][idx][0], c1 = Sacc[mt][idx][1];
                    float c2 = Sacc[mt][idx][2], c3 = Sacc[mt][idx][3];
                    if (diag) {
                        if (sg     >= t0 + r0) c0 = 0.0f;
                        if (sg + 1 >= t0 + r0) c1 = 0.0f;
                        if (sg     >= t0 + r1) c2 = 0.0f;
                        if (sg + 1 >= t0 + r1) c3 = 0.0f;
                    }
                    float h0 = __half2float(__float2half(c0));
                    float h1 = __half2float(__float2half(c1));
                    float h2 = __half2float(__float2half(c2));
                    float h3 = __half2float(__float2half(c3));
                    const uint32_t base = sb + SM_S + (uint32_t)wn * 16384u;
                    const uint32_t o0 = swz((uint32_t)(r0 * 128 + cloc * 2));
                    const uint32_t o1 = swz((uint32_t)(r1 * 128 + cloc * 2));
                    sts32(base + o0,          pack_h2(h0, h1));
                    sts32(base + o1,          pack_h2(h2, h3));
                    sts32(base + 32768u + o0, pack_h2(c0 - h0, c1 - h1));
                    sts32(base + 32768u + o1, pack_h2(c2 - h2, c3 - h3));
                }
            }
            __syncthreads();

            // ---- stage 2: O += Sh@Vh + Sh@Vl + Sl@Vh ----
#pragma unroll
            for (int ks8 = 0; ks8 < 8; ++ks8) {
                const int ksub = ks8 >> 2;
                const int kmin = ksub * 64 + (ks8 & 3) * 16;   // s offset of block
                if (diag && (kmin >= wm * 32 + 32)) continue;  // all-zero S rows
                const int kb   = (ks8 & 3) * 32 + lgrp * 16;
                const uint32_t tS = sb + SM_S + (uint32_t)ksub * 16384u;
                const uint32_t tV = sb + SM_V + (uint32_t)ksub * 16384u;
                uint32_t aH[2][4], aL[2][4];
#pragma unroll
                for (int mt = 0; mt < 2; ++mt) {
                    uint32_t ro = (uint32_t)((wm * 32 + mt * 16 + lrow) * 128 + kb);
                    ldsm4(aH[mt][0], aH[mt][1], aH[mt][2], aH[mt][3], tS + swz(ro));
                    ldsm4(aL[mt][0], aL[mt][1], aL[mt][2], aL[mt][3],
                          tS + 32768u + swz(ro));
                }
#pragma unroll
                for (int half = 0; half < 2; ++half) {
                    uint32_t bH[4][2], bL[4][2];
#pragma unroll
                    for (int pq = 0; pq < 2; ++pq) {
                        uint32_t ro = (uint32_t)((wn * 64 + half * 32 + pq * 16 + lrow) * 128 + kb);
                        uint32_t r0, r1, r2, r3;
                        ldsm4(r0, r1, r2, r3, tV + swz(ro));
                        bH[2 * pq][0] = r0; bH[2 * pq][1] = r2;
                        bH[2 * pq + 1][0] = r1; bH[2 * pq + 1][1] = r3;
                        ldsm4(r0, r1, r2, r3, tV + 32768u + swz(ro));
                        bL[2 * pq][0] = r0; bL[2 * pq][1] = r2;
                        bL[2 * pq + 1][0] = r1; bL[2 * pq + 1][1] = r3;
                    }
#pragma unroll
                    for (int mt = 0; mt < 2; ++mt) {
                        if (diag && (kmin >= wm * 32 + mt * 16 + 16)) continue;
#pragma unroll
                        for (int nt = 0; nt < 4; ++nt) {
                            float* cp = Oacc[mt][half * 4 + nt];
                            mma_fp16(cp, aH[mt][0], aH[mt][1], aH[mt][2], aH[mt][3],
                                     bH[nt][0], bH[nt][1]);
                            mma_fp16(cp, aH[mt][0], aH[mt][1], aH[mt][2], aH[mt][3],
                                     bL[nt][0], bL[nt][1]);
                            mma_fp16(cp, aL[mt][0], aL[mt][1], aL[mt][2], aL[mt][3],
                                     bH[nt][0], bH[nt][1]);
                        }
                    }
                }
            }
            __syncthreads();   // S/V consumed before next s-tile overwrites
        }

        // ---- O writeback for this t-tile ----
#pragma unroll
        for (int mt = 0; mt < 2; ++mt) {
            const int r0 = t0 + wm * 32 + mt * 16 + qr;
            const int r1 = r0 + 8;
#pragma unroll
            for (int idx = 0; idx < 8; ++idx) {
                const int d = wn * 64 + (idx >> 2) * 32 + (idx & 3) * 8 + qc;
                *(float2*)(Ob + (size_t)r0 * D_ + d) =
                    make_float2(Oacc[mt][idx][0], Oacc[mt][idx][1]);
                *(float2*)(Ob + (size_t)r1 * D_ + d) =
                    make_float2(Oacc[mt][idx][2], Oacc[mt][idx][3]);
            }
        }
    }
}

// ---------------------------------------------------------------------------
extern "C" void kernel_launch(void* const* d_in, const int* in_sizes, int n_in,
                              void* d_out, int out_size) {
    const float* Q = (const float*)d_in[0];
    const float* V = (const float*)d_in[2];   // d_in[1] is K == Q
    float* O = (float*)d_out;

    const size_t npairs = (size_t)BH * T_ * (N_ / 2);
    rope_split_kernel<<<(int)((npairs + NTH - 1) / NTH), NTH>>>(Q);

    const size_t nvt = (size_t)BH * D_ * T_;
    vt_split_kernel<<<(int)((nvt + NTH - 1) / NTH), NTH>>>(V);

    cudaFuncSetAttribute(attn_mma_kernel,
                         cudaFuncAttributeMaxDynamicSharedMemorySize, SM_TOT);
    attn_mma_kernel<<<9 * BH, NTH, SM_TOT>>>(O);
}

// round 8
// speedup vs baseline: 3.4782x; 1.4851x over previous
#include <cuda_runtime.h>
#include <cuda_fp16.h>
#include <cstdint>

#define BH   16
#define T_   2048
#define N_   1024
#define D_   128
#define TM   128          // t-rows per CTA tile
#define TSN  128          // s-cols per CTA tile
#define KC   64           // k-chunk (fp16 elems)
#define NCH  16           // N_/KC
#define NTT  16           // T_/TM
#define NTH  256

// ---------------- global scratch (static device alloc — allowed) ----------
__device__ __half g_QH[(size_t)BH * T_ * N_];   // 64 MiB (RoPE'd Q, fp16)
__device__ __half g_VTH[(size_t)BH * D_ * T_];  //  8 MiB (V^T hi)
__device__ __half g_VTL[(size_t)BH * D_ * T_];  //  8 MiB (V^T lo residual)

// ---------------- helpers --------------------------------------------------
__device__ __forceinline__ uint32_t smem_u32(const void* p) {
    uint32_t a;
    asm("{ .reg .u64 t; cvta.to.shared.u64 t, %1; cvt.u32.u64 %0, t; }"
        : "=r"(a) : "l"(p));
    return a;
}
__device__ __forceinline__ uint32_t swz(uint32_t off) {   // SW128 swizzle
    return off ^ ((off >> 3) & 0x70);
}
__device__ __forceinline__ void cp16(uint32_t sdst, const void* g) {
    asm volatile("cp.async.cg.shared.global [%0], [%1], 16;\n"
                 :: "r"(sdst), "l"(g) : "memory");
}
#define CP_COMMIT() asm volatile("cp.async.commit_group;\n" ::: "memory")
#define CP_WAIT1()  asm volatile("cp.async.wait_group 1;\n" ::: "memory")
#define CP_WAIT2()  asm volatile("cp.async.wait_group 2;\n" ::: "memory")

__device__ __forceinline__ void ldsm4(uint32_t& r0, uint32_t& r1,
                                      uint32_t& r2, uint32_t& r3, uint32_t a) {
    asm volatile("ldmatrix.sync.aligned.m8n8.x4.shared.b16 {%0,%1,%2,%3}, [%4];"
                 : "=r"(r0), "=r"(r1), "=r"(r2), "=r"(r3) : "r"(a));
}
__device__ __forceinline__ void mma_fp16(float c[4],
        uint32_t a0, uint32_t a1, uint32_t a2, uint32_t a3,
        uint32_t b0, uint32_t b1) {
    asm volatile(
        "mma.sync.aligned.m16n8k16.row.col.f32.f16.f16.f32 "
        "{%0,%1,%2,%3}, {%4,%5,%6,%7}, {%8,%9}, {%0,%1,%2,%3};"
        : "+f"(c[0]), "+f"(c[1]), "+f"(c[2]), "+f"(c[3])
        : "r"(a0), "r"(a1), "r"(a2), "r"(a3), "r"(b0), "r"(b1));
}
__device__ __forceinline__ void sts32(uint32_t addr, uint32_t v) {
    asm volatile("st.shared.b32 [%0], %1;" :: "r"(addr), "r"(v) : "memory");
}
__device__ __forceinline__ uint32_t pack_h2(float lo, float hi) {
    __half2 h = __floats2half2_rn(lo, hi);
    return *reinterpret_cast<uint32_t*>(&h);
}

// ---------------- prep 1: RoPE + fp16 quantize ----------------------------
__global__ void rope_split_kernel(const float* __restrict__ Q) {
    size_t idx = (size_t)blockIdx.x * blockDim.x + threadIdx.x;  // pair index
    const size_t npairs = (size_t)BH * T_ * (N_ / 2);
    if (idx >= npairs) return;
    int    n2  = (int)(idx % (N_ / 2));
    size_t row = idx / (N_ / 2);
    int    t   = (int)(row % T_);

    float pos  = (float)(2 * n2);
    float freq = exp2f(-16.0f * pos * (1.0f / (float)N_)) * 0.15915494309189535f;
    float r    = (float)t * freq;
    float ph   = (r - floorf(r)) * 6.283185307179586f;
    float s, c;
    __sincosf(ph, &s, &c);

    const float2 q = ((const float2*)Q)[idx];
    float ox = q.x * c - q.y * s;
    float oy = q.y * c + q.x * s;
    ((__half2*)g_QH)[idx] = __floats2half2_rn(ox, oy);
}

// ---------------- prep 2: V transpose + fp16 hi/lo split ------------------
__global__ void vt_split_kernel(const float* __restrict__ V) {
    size_t idx = (size_t)blockIdx.x * blockDim.x + threadIdx.x;  // [bh][d][t]
    const size_t tot = (size_t)BH * D_ * T_;
    if (idx >= tot) return;
    int    t   = (int)(idx % T_);
    size_t r   = idx / T_;
    int    d   = (int)(r % D_);
    size_t bh  = r / D_;
    float v = V[(bh * T_ + t) * D_ + d];
    __half h = __float2half(v);
    g_VTH[idx] = h;
    g_VTL[idx] = __float2half(v - __half2float(h));
}

// ---------------- attention (mma.sync fp16, 1-product stage1) -------------
// smem map (bytes):
//   [0, 64K)     : Q chunk double buffer, buf b at b*32768:
//                  QtH(+0) QsH(+16K), each [128 rows][64 k] fp16
//   [64K, 128K)  : V tiles: VH0 VH1 VL0 VL1, each [128 d][64 t] fp16
//   [128K, 192K) : S tiles: SH0 SH1 (+0,+16K), SL0 SL1 (+32K,+48K)
#define SM_V   65536
#define SM_S   131072
#define SM_TOT 196608

__device__ __forceinline__ void load_q_chunk(
    uint32_t sb, int buf, int k0, int t0, int s0, int tid,
    const __half* QHb) {
    int tsel = tid >> 7;        // 0: QtH, 1: QsH
    int u    = tid & 127;
    const __half* src = QHb + (size_t)(tsel ? s0 : t0) * N_ + k0;
    uint32_t tb = sb + (uint32_t)buf * 32768u + (uint32_t)tsel * 16384u;
#pragma unroll
    for (int i = 0; i < 8; ++i) {
        int idx = u * 8 + i;               // 0..1023 (16B units)
        int r = idx >> 3, c16 = idx & 7;
        cp16(tb + swz((uint32_t)(r * 128 + c16 * 16)),
             src + (size_t)r * N_ + c16 * 8);
    }
}

__device__ __forceinline__ void load_v_tile(
    uint32_t sb, int s0, int tid,
    const __half* VHb, const __half* VLb) {
    int tsel = tid >> 6;        // 0:VH0 1:VH1 2:VL0 3:VL1
    int u    = tid & 63;
    const __half* src =
        ((tsel < 2) ? VHb : VLb) + (size_t)(s0 + (tsel & 1) * 64);
    uint32_t tb = sb + SM_V + (uint32_t)tsel * 16384u;
#pragma unroll
    for (int i = 0; i < 16; ++i) {
        int idx = u * 16 + i;
        int r = idx >> 3, c16 = idx & 7;
        cp16(tb + swz((uint32_t)(r * 128 + c16 * 16)),
             src + (size_t)r * T_ + c16 * 8);
    }
}

__global__ void __launch_bounds__(NTH, 1)
attn_mma_kernel(float* __restrict__ O) {
    extern __shared__ char smem[];
    uint32_t sb = smem_u32(smem);
    const int tid  = threadIdx.x;
    const int wid  = tid >> 5;
    const int lane = tid & 31;
    const int wm   = wid & 3;         // m (t-row) group: 32 rows
    const int wn   = wid >> 2;        // n group: 64 cols
    const int lrow = lane & 15;       // ldmatrix row-within-16
    const int lgrp = lane >> 4;       // ldmatrix 16B-column select
    const int qr   = lane >> 2;       // C-frag row within 8
    const int qc   = (lane & 3) << 1; // C-frag col pair

    const int bh = blockIdx.x / 9;
    const int c  = blockIdx.x % 9;

    int tts[2]; int nrep;
    if (c == 0)      { tts[0] = 15; tts[1] = 15; nrep = 1; }
    else if (c == 8) { tts[0] = 7;  tts[1] = 7;  nrep = 1; }
    else             { tts[0] = 15 - c; tts[1] = c - 1; nrep = 2; }

    const __half* QHb = g_QH  + (size_t)bh * T_ * N_;
    const __half* VHb = g_VTH + (size_t)bh * D_ * T_;
    const __half* VLb = g_VTL + (size_t)bh * D_ * T_;
    float* Ob = O + (size_t)bh * T_ * D_;

    // prologue: first chunk of first s-tile into buf0
    load_q_chunk(sb, 0, 0, tts[0] * TM, 0, tid, QHb);
    CP_COMMIT();

    for (int rep = 0; rep < nrep; ++rep) {
        const int tt = tts[rep];
        const int t0 = tt * TM;

        float Oacc[2][8][4];
#pragma unroll
        for (int a = 0; a < 2; ++a)
#pragma unroll
            for (int b = 0; b < 8; ++b)
#pragma unroll
                for (int x = 0; x < 4; ++x) Oacc[a][b][x] = 0.0f;

        for (int st = 0; st <= tt; ++st) {
            const int s0 = st * TSN;
            const bool diag = (st == tt);
            const bool wskip = diag && (wn * 64 >= wm * 32 + 32);

            load_v_tile(sb, s0, tid, VHb, VLb);
            CP_COMMIT();

            float Sacc[2][8][4];
#pragma unroll
            for (int a = 0; a < 2; ++a)
#pragma unroll
                for (int b = 0; b < 8; ++b)
#pragma unroll
                    for (int x = 0; x < 4; ++x) Sacc[a][b][x] = 0.0f;

            // ---- stage 1: S = QtH @ QsH^T, 16 double-buffered chunks ----
            for (int cc = 0; cc < NCH; ++cc) {
                if (cc + 1 < NCH) {
                    load_q_chunk(sb, (cc + 1) & 1, (cc + 1) * KC, t0, s0, tid, QHb);
                } else if (st < tt) {           // prefetch next s-tile chunk0
                    load_q_chunk(sb, 0, 0, t0, s0 + TSN, tid, QHb);
                } else if (rep + 1 < nrep) {    // prefetch next t-tile chunk0
                    load_q_chunk(sb, 0, 0, tts[rep + 1] * TM, 0, tid, QHb);
                }
                CP_COMMIT();
                if (cc == 0) { CP_WAIT2(); } else { CP_WAIT1(); }
                __syncthreads();

                if (!wskip) {
                    const uint32_t qb = sb + (uint32_t)(cc & 1) * 32768u;
#pragma unroll
                    for (int ks = 0; ks < 4; ++ks) {
                        const int kb = ks * 32 + lgrp * 16;
                        uint32_t aH[2][4];
#pragma unroll
                        for (int mt = 0; mt < 2; ++mt) {
                            uint32_t ro = (uint32_t)((wm * 32 + mt * 16 + lrow) * 128 + kb);
                            ldsm4(aH[mt][0], aH[mt][1], aH[mt][2], aH[mt][3],
                                  qb + swz(ro));
                        }
#pragma unroll
                        for (int half = 0; half < 2; ++half) {
                            if (diag && (wn * 64 + half * 32 >= wm * 32 + 32)) continue;
                            uint32_t bH[4][2];
#pragma unroll
                            for (int pq = 0; pq < 2; ++pq) {
                                uint32_t ro = (uint32_t)((wn * 64 + half * 32 + pq * 16 + lrow) * 128 + kb);
                                uint32_t r0, r1, r2, r3;
                                ldsm4(r0, r1, r2, r3, qb + 16384u + swz(ro));
                                bH[2 * pq][0] = r0; bH[2 * pq][1] = r2;
                                bH[2 * pq + 1][0] = r1; bH[2 * pq + 1][1] = r3;
                            }
#pragma unroll
                            for (int mt = 0; mt < 2; ++mt)
#pragma unroll
                                for (int nt = 0; nt < 4; ++nt) {
                                    if (diag && (wn * 64 + half * 32 + nt * 8 >=
                                                 wm * 32 + mt * 16 + 16)) continue;
                                    mma_fp16(Sacc[mt][half * 4 + nt],
                                             aH[mt][0], aH[mt][1], aH[mt][2],
                                             aH[mt][3], bH[nt][0], bH[nt][1]);
                                }
                        }
                    }
                }
                __syncthreads();
            }

            // ---- mask + fp16 hi/lo split of S into smem ----
#pragma unroll
            for (int mt = 0; mt < 2; ++mt) {
                const int r0 = wm * 32 + mt * 16 + qr;   // tile-local t rows
                const int r1 = r0 + 8;
#pragma unroll
                for (int idx = 0; idx < 8; ++idx) {
                    const int cloc = (idx >> 2) * 32 + (idx & 3) * 8 + qc;  // 0..63
                    const int sg = s0 + wn * 64 + cloc;
                    float c0 = Sacc[mt][idx][0], c1 = Sacc[mt][idx][1];
                    float c2 = Sacc[mt][idx][2], c3 = Sacc[mt][idx][3];
                    if (diag) {
                        if (sg     >= t0 + r0) c0 = 0.0f;
                        if (sg + 1 >= t0 + r0) c1 = 0.0f;
                        if (sg     >= t0 + r1) c2 = 0.0f;
                        if (sg + 1 >= t0 + r1) c3 = 0.0f;
                    }
                    float h0 = __half2float(__float2half(c0));
                    float h1 = __half2float(__float2half(c1));
                    float h2 = __half2float(__float2half(c2));
                    float h3 = __half2float(__float2half(c3));
                    const uint32_t base = sb + SM_S + (uint32_t)wn * 16384u;
                    const uint32_t o0 = swz((uint32_t)(r0 * 128 + cloc * 2));
                    const uint32_t o1 = swz((uint32_t)(r1 * 128 + cloc * 2));
                    sts32(base + o0,          pack_h2(h0, h1));
                    sts32(base + o1,          pack_h2(h2, h3));
                    sts32(base + 32768u + o0, pack_h2(c0 - h0, c1 - h1));
                    sts32(base + 32768u + o1, pack_h2(c2 - h2, c3 - h3));
                }
            }
            __syncthreads();

            // ---- stage 2: O += Sh@Vh + Sh@Vl + Sl@Vh ----
#pragma unroll
            for (int ks8 = 0; ks8 < 8; ++ks8) {
                const int ksub = ks8 >> 2;
                const int kmin = ksub * 64 + (ks8 & 3) * 16;   // s offset of block
                if (diag && (kmin >= wm * 32 + 32)) continue;  // all-zero S rows
                const int kb   = (ks8 & 3) * 32 + lgrp * 16;
                const uint32_t tS = sb + SM_S + (uint32_t)ksub * 16384u;
                const uint32_t tV = sb + SM_V + (uint32_t)ksub * 16384u;
                uint32_t aH[2][4], aL[2][4];
#pragma unroll
                for (int mt = 0; mt < 2; ++mt) {
                    uint32_t ro = (uint32_t)((wm * 32 + mt * 16 + lrow) * 128 + kb);
                    ldsm4(aH[mt][0], aH[mt][1], aH[mt][2], aH[mt][3], tS + swz(ro));
                    ldsm4(aL[mt][0], aL[mt][1], aL[mt][2], aL[mt][3],
                          tS + 32768u + swz(ro));
                }
#pragma unroll
                for (int half = 0; half < 2; ++half) {
                    uint32_t bH[4][2], bL[4][2];
#pragma unroll
                    for (int pq = 0; pq < 2; ++pq) {
                        uint32_t ro = (uint32_t)((wn * 64 + half * 32 + pq * 16 + lrow) * 128 + kb);
                        uint32_t r0, r1, r2, r3;
                        ldsm4(r0, r1, r2, r3, tV + swz(ro));
                        bH[2 * pq][0] = r0; bH[2 * pq][1] = r2;
                        bH[2 * pq + 1][0] = r1; bH[2 * pq + 1][1] = r3;
                        ldsm4(r0, r1, r2, r3, tV + 32768u + swz(ro));
                        bL[2 * pq][0] = r0; bL[2 * pq][1] = r2;
                        bL[2 * pq + 1][0] = r1; bL[2 * pq + 1][1] = r3;
                    }
#pragma unroll
                    for (int mt = 0; mt < 2; ++mt) {
                        if (diag && (kmin >= wm * 32 + mt * 16 + 16)) continue;
#pragma unroll
                        for (int nt = 0; nt < 4; ++nt) {
                            float* cp = Oacc[mt][half * 4 + nt];
                            mma_fp16(cp, aH[mt][0], aH[mt][1], aH[mt][2], aH[mt][3],
                                     bH[nt][0], bH[nt][1]);
                            mma_fp16(cp, aH[mt][0], aH[mt][1], aH[mt][2], aH[mt][3],
                                     bL[nt][0], bL[nt][1]);
                            mma_fp16(cp, aL[mt][0], aL[mt][1], aL[mt][2], aL[mt][3],
                                     bH[nt][0], bH[nt][1]);
                        }
                    }
                }
            }
            __syncthreads();   // S/V consumed before next s-tile overwrites
        }

        // ---- O writeback for this t-tile ----
#pragma unroll
        for (int mt = 0; mt < 2; ++mt) {
            const int r0 = t0 + wm * 32 + mt * 16 + qr;
            const int r1 = r0 + 8;
#pragma unroll
            for (int idx = 0; idx < 8; ++idx) {
                const int d = wn * 64 + (idx >> 2) * 32 + (idx & 3) * 8 + qc;
                *(float2*)(Ob + (size_t)r0 * D_ + d) =
                    make_float2(Oacc[mt][idx][0], Oacc[mt][idx][1]);
                *(float2*)(Ob + (size_t)r1 * D_ + d) =
                    make_float2(Oacc[mt][idx][2], Oacc[mt][idx][3]);
            }
        }
    }
}

// ---------------------------------------------------------------------------
extern "C" void kernel_launch(void* const* d_in, const int* in_sizes, int n_in,
                              void* d_out, int out_size) {
    const float* Q = (const float*)d_in[0];
    const float* V = (const float*)d_in[2];   // d_in[1] is K == Q
    float* O = (float*)d_out;

    const size_t npairs = (size_t)BH * T_ * (N_ / 2);
    rope_split_kernel<<<(int)((npairs + NTH - 1) / NTH), NTH>>>(Q);

    const size_t nvt = (size_t)BH * D_ * T_;
    vt_split_kernel<<<(int)((nvt + NTH - 1) / NTH), NTH>>>(V);

    cudaFuncSetAttribute(attn_mma_kernel,
                         cudaFuncAttributeMaxDynamicSharedMemorySize, SM_TOT);
    attn_mma_kernel<<<9 * BH, NTH, SM_TOT>>>(O);
}

// round 9
// speedup vs baseline: 3.8814x; 1.1159x over previous
#include <cuda_runtime.h>
#include <cuda_fp16.h>
#include <cstdint>

#define BH   16
#define T_   2048
#define N_   1024
#define D_   128
#define TM   128          // t-rows per CTA tile
#define TSN  128          // s-cols per CTA tile
#define KC   128          // k-chunk (fp16 elems)
#define NCH  8            // N_/KC
#define NTT  16           // T_/TM
#define NTH  256

// ---------------- global scratch (static device alloc — allowed) ----------
__device__ __half g_QH[(size_t)BH * T_ * N_];   // 64 MiB (RoPE'd Q, fp16)
__device__ __half g_VTH[(size_t)BH * D_ * T_];  //  8 MiB (V^T, fp16)

// ---------------- helpers --------------------------------------------------
__device__ __forceinline__ uint32_t smem_u32(const void* p) {
    uint32_t a;
    asm("{ .reg .u64 t; cvta.to.shared.u64 t, %1; cvt.u32.u64 %0, t; }"
        : "=r"(a) : "l"(p));
    return a;
}
__device__ __forceinline__ uint32_t swz(uint32_t off) {   // SW128 swizzle
    return off ^ ((off >> 3) & 0x70);
}
__device__ __forceinline__ void cp16(uint32_t sdst, const void* g) {
    asm volatile("cp.async.cg.shared.global [%0], [%1], 16;\n"
                 :: "r"(sdst), "l"(g) : "memory");
}
#define CP_COMMIT() asm volatile("cp.async.commit_group;\n" ::: "memory")
#define CP_WAIT1()  asm volatile("cp.async.wait_group 1;\n" ::: "memory")
#define CP_WAIT2()  asm volatile("cp.async.wait_group 2;\n" ::: "memory")

__device__ __forceinline__ void ldsm4(uint32_t& r0, uint32_t& r1,
                                      uint32_t& r2, uint32_t& r3, uint32_t a) {
    asm volatile("ldmatrix.sync.aligned.m8n8.x4.shared.b16 {%0,%1,%2,%3}, [%4];"
                 : "=r"(r0), "=r"(r1), "=r"(r2), "=r"(r3) : "r"(a));
}
__device__ __forceinline__ void mma_fp16(float c[4],
        uint32_t a0, uint32_t a1, uint32_t a2, uint32_t a3,
        uint32_t b0, uint32_t b1) {
    asm volatile(
        "mma.sync.aligned.m16n8k16.row.col.f32.f16.f16.f32 "
        "{%0,%1,%2,%3}, {%4,%5,%6,%7}, {%8,%9}, {%0,%1,%2,%3};"
        : "+f"(c[0]), "+f"(c[1]), "+f"(c[2]), "+f"(c[3])
        : "r"(a0), "r"(a1), "r"(a2), "r"(a3), "r"(b0), "r"(b1));
}
__device__ __forceinline__ void sts32(uint32_t addr, uint32_t v) {
    asm volatile("st.shared.b32 [%0], %1;" :: "r"(addr), "r"(v) : "memory");
}
__device__ __forceinline__ uint32_t pack_h2(float lo, float hi) {
    __half2 h = __floats2half2_rn(lo, hi);
    return *reinterpret_cast<uint32_t*>(&h);
}

// ---------------- prep 1: RoPE + fp16 quantize ----------------------------
__global__ void rope_split_kernel(const float* __restrict__ Q) {
    uint32_t idx = blockIdx.x * blockDim.x + threadIdx.x;  // pair index
    const uint32_t npairs = (uint32_t)BH * T_ * (N_ / 2);
    if (idx >= npairs) return;
    uint32_t n2 = idx & 511u;            // N_/2 = 512
    uint32_t t  = (idx >> 9) & 2047u;    // T_ = 2048

    float pos  = (float)(2u * n2);
    float freq = exp2f(-16.0f * pos * (1.0f / (float)N_)) * 0.15915494309189535f;
    float r    = (float)t * freq;
    float ph   = (r - floorf(r)) * 6.283185307179586f;
    float s, c;
    __sincosf(ph, &s, &c);

    const float2 q = ((const float2*)Q)[idx];
    float ox = q.x * c - q.y * s;
    float oy = q.y * c + q.x * s;
    ((__half2*)g_QH)[idx] = __floats2half2_rn(ox, oy);
}

// ---------------- prep 2: V transpose + fp16 quantize ---------------------
__global__ void vt_split_kernel(const float* __restrict__ V) {
    uint32_t idx = blockIdx.x * blockDim.x + threadIdx.x;  // [bh][d][t]
    const uint32_t tot = (uint32_t)BH * D_ * T_;
    if (idx >= tot) return;
    uint32_t t  = idx & 2047u;           // T_ = 2048
    uint32_t r  = idx >> 11;
    uint32_t d  = r & 127u;              // D_ = 128
    uint32_t bh = r >> 7;
    float v = V[((size_t)bh * T_ + t) * D_ + d];
    g_VTH[idx] = __float2half(v);
}

// ---------------- attention (mma.sync fp16, single-product) ---------------
// smem map (bytes):
//   [0, 128K)    : Q chunk double buffer, buf b at b*65536:
//                  Qt_sub0(+0) Qt_sub1(+16K) Qs_sub0(+32K) Qs_sub1(+48K)
//                  each subtile [128 rows][64 k] fp16, SW128
//   [128K, 160K) : V tile: V_sub0(+0) V_sub1(+16K), [128 d][64 t] each
//   [160K, 192K) : S tile: S_sub0(+0) S_sub1(+16K), [128 t][64 s] each
#define SM_V   131072
#define SM_S   163840
#define SM_TOT 196608

__device__ __forceinline__ void load_q_chunk(
    uint32_t sb, int buf, int k0, int t0, int s0, int tid,
    const __half* QHb) {
    int tsel = tid >> 7;        // 0: Qt, 1: Qs
    int u    = tid & 127;
    const __half* src = QHb + (size_t)(tsel ? s0 : t0) * N_ + k0;
    uint32_t tb = sb + (uint32_t)buf * 65536u + (uint32_t)tsel * 32768u;
#pragma unroll
    for (int i = 0; i < 16; ++i) {
        int idx = u * 16 + i;              // 0..2047 (16B units), 16/row
        int r = idx >> 4, c16 = idx & 15;
        cp16(tb + (uint32_t)((c16 >> 3) * 16384) +
                 swz((uint32_t)(r * 128 + (c16 & 7) * 16)),
             src + (size_t)r * N_ + c16 * 8);
    }
}

__device__ __forceinline__ void load_v_tile(
    uint32_t sb, int s0, int tid, const __half* VHb) {
    int u = tid;
#pragma unroll
    for (int i = 0; i < 8; ++i) {
        int idx = u * 8 + i;               // 0..2047 (16B units), 16/row
        int r = idx >> 4, c16 = idx & 15;
        cp16(sb + SM_V + (uint32_t)((c16 >> 3) * 16384) +
                 swz((uint32_t)(r * 128 + (c16 & 7) * 16)),
             VHb + (size_t)r * T_ + s0 + c16 * 8);
    }
}

__global__ void __launch_bounds__(NTH, 1)
attn_mma_kernel(float* __restrict__ O) {
    extern __shared__ char smem[];
    uint32_t sb = smem_u32(smem);
    const int tid  = threadIdx.x;
    const int wid  = tid >> 5;
    const int lane = tid & 31;
    const int wm   = wid & 3;         // m (t-row) group: 32 rows
    const int wn   = wid >> 2;        // n group: 64 cols
    const int lrow = lane & 15;       // ldmatrix row-within-16
    const int lgrp = lane >> 4;       // ldmatrix 16B-column select
    const int qr   = lane >> 2;       // C-frag row within 8
    const int qc   = (lane & 3) << 1; // C-frag col pair

    const int bh = blockIdx.x / 9;
    const int c  = blockIdx.x % 9;

    int tts[2]; int nrep;
    if (c == 0)      { tts[0] = 15; tts[1] = 15; nrep = 1; }
    else if (c == 8) { tts[0] = 7;  tts[1] = 7;  nrep = 1; }
    else             { tts[0] = 15 - c; tts[1] = c - 1; nrep = 2; }

    const __half* QHb = g_QH  + (size_t)bh * T_ * N_;
    const __half* VHb = g_VTH + (size_t)bh * D_ * T_;
    float* Ob = O + (size_t)bh * T_ * D_;

    // prologue: first chunk of first s-tile into buf0
    load_q_chunk(sb, 0, 0, tts[0] * TM, 0, tid, QHb);
    CP_COMMIT();

    for (int rep = 0; rep < nrep; ++rep) {
        const int tt = tts[rep];
        const int t0 = tt * TM;

        float Oacc[2][8][4];
#pragma unroll
        for (int a = 0; a < 2; ++a)
#pragma unroll
            for (int b = 0; b < 8; ++b)
#pragma unroll
                for (int x = 0; x < 4; ++x) Oacc[a][b][x] = 0.0f;

        for (int st = 0; st <= tt; ++st) {
            const int s0 = st * TSN;
            const bool diag = (st == tt);
            const bool wskip = diag && (wn * 64 >= wm * 32 + 32);

            load_v_tile(sb, s0, tid, VHb);
            CP_COMMIT();

            float Sacc[2][8][4];
#pragma unroll
            for (int a = 0; a < 2; ++a)
#pragma unroll
                for (int b = 0; b < 8; ++b)
#pragma unroll
                    for (int x = 0; x < 4; ++x) Sacc[a][b][x] = 0.0f;

            // ---- stage 1: S = Qt @ Qs^T, 8 double-buffered K=128 chunks ----
            for (int cc = 0; cc < NCH; ++cc) {
                if (cc + 1 < NCH) {
                    load_q_chunk(sb, (cc + 1) & 1, (cc + 1) * KC, t0, s0, tid, QHb);
                } else if (st < tt) {           // prefetch next s-tile chunk0
                    load_q_chunk(sb, 0, 0, t0, s0 + TSN, tid, QHb);
                } else if (rep + 1 < nrep) {    // prefetch next t-tile chunk0
                    load_q_chunk(sb, 0, 0, tts[rep + 1] * TM, 0, tid, QHb);
                }
                CP_COMMIT();
                if (cc == 0) { CP_WAIT2(); } else { CP_WAIT1(); }
                __syncthreads();

                if (!wskip) {
                    const uint32_t qb = sb + (uint32_t)(cc & 1) * 65536u;
#pragma unroll
                    for (int ks = 0; ks < 8; ++ks) {
                        const uint32_t qtb = qb + (uint32_t)((ks >> 2) * 16384);
                        const uint32_t qsb = qb + 32768u + (uint32_t)((ks >> 2) * 16384);
                        const int kb = (ks & 3) * 32 + lgrp * 16;
                        uint32_t aH[2][4];
#pragma unroll
                        for (int mt = 0; mt < 2; ++mt) {
                            uint32_t ro = (uint32_t)((wm * 32 + mt * 16 + lrow) * 128 + kb);
                            ldsm4(aH[mt][0], aH[mt][1], aH[mt][2], aH[mt][3],
                                  qtb + swz(ro));
                        }
#pragma unroll
                        for (int half = 0; half < 2; ++half) {
                            if (diag && (wn * 64 + half * 32 >= wm * 32 + 32)) continue;
                            uint32_t bH[4][2];
#pragma unroll
                            for (int pq = 0; pq < 2; ++pq) {
                                uint32_t ro = (uint32_t)((wn * 64 + half * 32 + pq * 16 + lrow) * 128 + kb);
                                uint32_t r0, r1, r2, r3;
                                ldsm4(r0, r1, r2, r3, qsb + swz(ro));
                                bH[2 * pq][0] = r0; bH[2 * pq][1] = r2;
                                bH[2 * pq + 1][0] = r1; bH[2 * pq + 1][1] = r3;
                            }
#pragma unroll
                            for (int mt = 0; mt < 2; ++mt)
#pragma unroll
                                for (int nt = 0; nt < 4; ++nt) {
                                    if (diag && (wn * 64 + half * 32 + nt * 8 >=
                                                 wm * 32 + mt * 16 + 16)) continue;
                                    mma_fp16(Sacc[mt][half * 4 + nt],
                                             aH[mt][0], aH[mt][1], aH[mt][2],
                                             aH[mt][3], bH[nt][0], bH[nt][1]);
                                }
                        }
                    }
                }
                __syncthreads();
            }

            // ---- mask + fp16 quantize of S into smem ----
#pragma unroll
            for (int mt = 0; mt < 2; ++mt) {
                const int r0 = wm * 32 + mt * 16 + qr;   // tile-local t rows
                const int r1 = r0 + 8;
#pragma unroll
                for (int idx = 0; idx < 8; ++idx) {
                    const int cloc = (idx >> 2) * 32 + (idx & 3) * 8 + qc;  // 0..63
                    const int sg = s0 + wn * 64 + cloc;
                    float c0 = Sacc[mt][idx][0], c1 = Sacc[mt][idx][1];
                    float c2 = Sacc[mt][idx][2], c3 = Sacc[mt][idx][3];
                    if (diag) {
                        if (sg     >= t0 + r0) c0 = 0.0f;
                        if (sg + 1 >= t0 + r0) c1 = 0.0f;
                        if (sg     >= t0 + r1) c2 = 0.0f;
                        if (sg + 1 >= t0 + r1) c3 = 0.0f;
                    }
                    const uint32_t base = sb + SM_S + (uint32_t)wn * 16384u;
                    sts32(base + swz((uint32_t)(r0 * 128 + cloc * 2)), pack_h2(c0, c1));
                    sts32(base + swz((uint32_t)(r1 * 128 + cloc * 2)), pack_h2(c2, c3));
                }
            }
            __syncthreads();

            // ---- stage 2: O += S @ V^T ----
#pragma unroll
            for (int ks8 = 0; ks8 < 8; ++ks8) {
                const int ksub = ks8 >> 2;
                const int kmin = ksub * 64 + (ks8 & 3) * 16;   // s offset of block
                if (diag && (kmin >= wm * 32 + 32)) continue;  // all-zero S rows
                const int kb   = (ks8 & 3) * 32 + lgrp * 16;
                const uint32_t tS = sb + SM_S + (uint32_t)ksub * 16384u;
                const uint32_t tV = sb + SM_V + (uint32_t)ksub * 16384u;
                uint32_t aH[2][4];
#pragma unroll
                for (int mt = 0; mt < 2; ++mt) {
                    uint32_t ro = (uint32_t)((wm * 32 + mt * 16 + lrow) * 128 + kb);
                    ldsm4(aH[mt][0], aH[mt][1], aH[mt][2], aH[mt][3], tS + swz(ro));
                }
#pragma unroll
                for (int half = 0; half < 2; ++half) {
                    uint32_t bH[4][2];
#pragma unroll
                    for (int pq = 0; pq < 2; ++pq) {
                        uint32_t ro = (uint32_t)((wn * 64 + half * 32 + pq * 16 + lrow) * 128 + kb);
                        uint32_t r0, r1, r2, r3;
                        ldsm4(r0, r1, r2, r3, tV + swz(ro));
                        bH[2 * pq][0] = r0; bH[2 * pq][1] = r2;
                        bH[2 * pq + 1][0] = r1; bH[2 * pq + 1][1] = r3;
                    }
#pragma unroll
                    for (int mt = 0; mt < 2; ++mt) {
                        if (diag && (kmin >= wm * 32 + mt * 16 + 16)) continue;
#pragma unroll
                        for (int nt = 0; nt < 4; ++nt) {
                            mma_fp16(Oacc[mt][half * 4 + nt],
                                     aH[mt][0], aH[mt][1], aH[mt][2], aH[mt][3],
                                     bH[nt][0], bH[nt][1]);
                        }
                    }
                }
            }
            __syncthreads();   // S/V consumed before next s-tile overwrites
        }

        // ---- O writeback for this t-tile ----
#pragma unroll
        for (int mt = 0; mt < 2; ++mt) {
            const int r0 = t0 + wm * 32 + mt * 16 + qr;
            const int r1 = r0 + 8;
#pragma unroll
            for (int idx = 0; idx < 8; ++idx) {
                const int d = wn * 64 + (idx >> 2) * 32 + (idx & 3) * 8 + qc;
                *(float2*)(Ob + (size_t)r0 * D_ + d) =
                    make_float2(Oacc[mt][idx][0], Oacc[mt][idx][1]);
                *(float2*)(Ob + (size_t)r1 * D_ + d) =
                    make_float2(Oacc[mt][idx][2], Oacc[mt][idx][3]);
            }
        }
    }
}

// ---------------------------------------------------------------------------
extern "C" void kernel_launch(void* const* d_in, const int* in_sizes, int n_in,
                              void* d_out, int out_size) {
    const float* Q = (const float*)d_in[0];
    const float* V = (const float*)d_in[2];   // d_in[1] is K == Q
    float* O = (float*)d_out;

    const size_t npairs = (size_t)BH * T_ * (N_ / 2);
    rope_split_kernel<<<(int)((npairs + NTH - 1) / NTH), NTH>>>(Q);

    const size_t nvt = (size_t)BH * D_ * T_;
    vt_split_kernel<<<(int)((nvt + NTH - 1) / NTH), NTH>>>(V);

    cudaFuncSetAttribute(attn_mma_kernel,
                         cudaFuncAttributeMaxDynamicSharedMemorySize, SM_TOT);
    attn_mma_kernel<<<9 * BH, NTH, SM_TOT>>>(O);
}

// round 10
// speedup vs baseline: 4.2331x; 1.0906x over previous
#include <cuda_runtime.h>
#include <cuda_fp16.h>
#include <cstdint>

#define BH   16
#define T_   2048
#define N_   1024
#define D_   128
#define TM   128          // t-rows per CTA tile
#define TSN  128          // s-cols per CTA tile
#define KC   128          // k-chunk (fp16 elems)
#define NCH  8            // N_/KC
#define NTT  16           // T_/TM
#define NTH  256

// ---------------- global scratch (static device alloc — allowed) ----------
__device__ __half g_QH[(size_t)BH * T_ * N_];   // 64 MiB (RoPE'd Q, fp16)
__device__ __half g_VTH[(size_t)BH * D_ * T_];  //  8 MiB (V^T, fp16)

// ---------------- helpers --------------------------------------------------
__device__ __forceinline__ uint32_t smem_u32(const void* p) {
    uint32_t a;
    asm("{ .reg .u64 t; cvta.to.shared.u64 t, %1; cvt.u32.u64 %0, t; }"
        : "=r"(a) : "l"(p));
    return a;
}
__device__ __forceinline__ uint32_t swz(uint32_t off) {   // SW128 swizzle
    return off ^ ((off >> 3) & 0x70);
}
__device__ __forceinline__ void cp16(uint32_t sdst, const void* g) {
    asm volatile("cp.async.cg.shared.global [%0], [%1], 16;\n"
                 :: "r"(sdst), "l"(g) : "memory");
}
#define CP_COMMIT() asm volatile("cp.async.commit_group;\n" ::: "memory")
#define CP_WAIT0()  asm volatile("cp.async.wait_group 0;\n" ::: "memory")

__device__ __forceinline__ void ldsm4(uint32_t& r0, uint32_t& r1,
                                      uint32_t& r2, uint32_t& r3, uint32_t a) {
    asm volatile("ldmatrix.sync.aligned.m8n8.x4.shared.b16 {%0,%1,%2,%3}, [%4];"
                 : "=r"(r0), "=r"(r1), "=r"(r2), "=r"(r3) : "r"(a));
}
__device__ __forceinline__ void mma_fp16(float c[4],
        uint32_t a0, uint32_t a1, uint32_t a2, uint32_t a3,
        uint32_t b0, uint32_t b1) {
    asm volatile(
        "mma.sync.aligned.m16n8k16.row.col.f32.f16.f16.f32 "
        "{%0,%1,%2,%3}, {%4,%5,%6,%7}, {%8,%9}, {%0,%1,%2,%3};"
        : "+f"(c[0]), "+f"(c[1]), "+f"(c[2]), "+f"(c[3])
        : "r"(a0), "r"(a1), "r"(a2), "r"(a3), "r"(b0), "r"(b1));
}
__device__ __forceinline__ uint32_t pack_h2(float lo, float hi) {
    __half2 h = __floats2half2_rn(lo, hi);
    return *reinterpret_cast<uint32_t*>(&h);
}

// ---------------- prep 1: RoPE + fp16 quantize (2 pairs / thread) ---------
__global__ void rope_split_kernel(const float* __restrict__ Q) {
    uint32_t i4 = blockIdx.x * blockDim.x + threadIdx.x;   // float4 index
    const uint32_t n4 = (uint32_t)BH * T_ * (N_ / 4);
    if (i4 >= n4) return;
    uint32_t p0 = 2u * i4;                 // first pair index
    uint32_t n2 = p0 & 511u;               // N_/2 = 512 pairs per row
    uint32_t t  = (p0 >> 9) & 2047u;

    const float4 q = ((const float4*)Q)[i4];
    float tf = (float)t;

    float pos0  = (float)(2u * n2);
    float f0 = exp2f(-16.0f * pos0 * (1.0f / (float)N_)) * 0.15915494309189535f;
    float r0 = tf * f0;
    float ph0 = (r0 - floorf(r0)) * 6.283185307179586f;
    float s0, c0; __sincosf(ph0, &s0, &c0);

    float pos1  = (float)(2u * (n2 + 1u));
    float f1 = exp2f(-16.0f * pos1 * (1.0f / (float)N_)) * 0.15915494309189535f;
    float r1 = tf * f1;
    float ph1 = (r1 - floorf(r1)) * 6.283185307179586f;
    float s1, c1; __sincosf(ph1, &s1, &c1);

    uint2 o;
    o.x = pack_h2(q.x * c0 - q.y * s0, q.y * c0 + q.x * s0);
    o.y = pack_h2(q.z * c1 - q.w * s1, q.w * c1 + q.z * s1);
    ((uint2*)g_QH)[i4] = o;
}

// ---------------- prep 2: coalesced tiled V transpose ---------------------
__global__ void vt_split_kernel(const float* __restrict__ V) {
    __shared__ float tile[32][33];
    const int t0 = blockIdx.x * 32;
    const int d0 = blockIdx.y * 32;
    const int bh = blockIdx.z;
    const int tx = threadIdx.x, ty = threadIdx.y;   // block (32, 8)

    const float* Vb = V + ((size_t)bh * T_) * D_;
#pragma unroll
    for (int i = 0; i < 4; ++i)
        tile[ty + i * 8][tx] = Vb[(size_t)(t0 + ty + i * 8) * D_ + d0 + tx];
    __syncthreads();

    __half* VTb = g_VTH + (size_t)bh * D_ * T_;
#pragma unroll
    for (int i = 0; i < 4; ++i)
        VTb[(size_t)(d0 + ty + i * 8) * T_ + t0 + tx] =
            __float2half(tile[tx][ty + i * 8]);
}

// ---------------- attention (mma.sync fp16, reg-resident S) ---------------
// smem map (bytes):
//   [0, 128K)    : Q chunk double buffer, buf b at b*65536:
//                  Qt_sub0(+0) Qt_sub1(+16K) Qs_sub0(+32K) Qs_sub1(+48K)
//                  each subtile [128 rows][64 k] fp16, SW128
//   [128K, 160K) : V tile: V_sub0(+0) V_sub1(+16K), [128 d][64 s] each
#define SM_V   131072
#define SM_TOT 163840

__device__ __forceinline__ void load_q_chunk(
    uint32_t sb, int buf, int k0, int t0, int s0, int tid,
    const __half* QHb) {
    int tsel = tid >> 7;        // 0: Qt, 1: Qs
    int u    = tid & 127;
    const __half* src = QHb + (size_t)(tsel ? s0 : t0) * N_ + k0;
    uint32_t tb = sb + (uint32_t)buf * 65536u + (uint32_t)tsel * 32768u;
#pragma unroll
    for (int i = 0; i < 16; ++i) {
        int idx = u * 16 + i;              // 0..2047 (16B units), 16/row
        int r = idx >> 4, c16 = idx & 15;
        cp16(tb + (uint32_t)((c16 >> 3) * 16384) +
                 swz((uint32_t)(r * 128 + (c16 & 7) * 16)),
             src + (size_t)r * N_ + c16 * 8);
    }
}

__device__ __forceinline__ void load_v_tile(
    uint32_t sb, int s0, int tid, const __half* VHb) {
    int u = tid;
#pragma unroll
    for (int i = 0; i < 8; ++i) {
        int idx = u * 8 + i;               // 0..2047 (16B units), 16/row
        int r = idx >> 4, c16 = idx & 15;
        cp16(sb + SM_V + (uint32_t)((c16 >> 3) * 16384) +
                 swz((uint32_t)(r * 128 + (c16 & 7) * 16)),
             VHb + (size_t)r * T_ + s0 + c16 * 8);
    }
}

__global__ void __launch_bounds__(NTH)
attn_mma_kernel(float* __restrict__ O) {
    extern __shared__ char smem[];
    uint32_t sb = smem_u32(smem);
    const int tid  = threadIdx.x;
    const int w    = tid >> 5;        // warp 0..7: owns t-rows [16w, 16w+16)
    const int lane = tid & 31;
    const int lrow = lane & 15;       // ldmatrix row-within-16
    const int lgrp = lane >> 4;       // ldmatrix 16B-column select
    const int qr   = lane >> 2;       // C/A-frag row within 8
    const int qc   = (lane & 3) << 1; // C/A-frag col pair

    const int bh = blockIdx.x / 9;
    const int c  = blockIdx.x % 9;

    int tts[2]; int nrep;
    if (c == 0)      { tts[0] = 15; tts[1] = 15; nrep = 1; }
    else if (c == 8) { tts[0] = 7;  tts[1] = 7;  nrep = 1; }
    else             { tts[0] = 15 - c; tts[1] = c - 1; nrep = 2; }

    const __half* QHb = g_QH  + (size_t)bh * T_ * N_;
    const __half* VHb = g_VTH + (size_t)bh * D_ * T_;
    float* Ob = O + (size_t)bh * T_ * D_;

    const int w16 = w * 16;

    // prologue: chunk0 of first s-tile into buf0
    load_q_chunk(sb, 0, 0, tts[0] * TM, 0, tid, QHb);
    CP_COMMIT();

    for (int rep = 0; rep < nrep; ++rep) {
        const int tt = tts[rep];
        const int t0 = tt * TM;

        float Oacc[16][4];
#pragma unroll
        for (int b = 0; b < 16; ++b)
#pragma unroll
            for (int x = 0; x < 4; ++x) Oacc[b][x] = 0.0f;

        for (int st = 0; st <= tt; ++st) {
            const int s0 = st * TSN;
            const bool diag = (st == tt);

            float Sacc[16][4];
#pragma unroll
            for (int b = 0; b < 16; ++b)
#pragma unroll
                for (int x = 0; x < 4; ++x) Sacc[b][x] = 0.0f;

            // ---- stage 1: S = Qt @ Qs^T, 8 double-buffered K=128 chunks --
            for (int cc = 0; cc < NCH; ++cc) {
                CP_WAIT0();
                __syncthreads();
                // issue next loads AFTER the barrier (WAR-safe)
                if (cc + 1 < NCH) {
                    load_q_chunk(sb, (cc + 1) & 1, (cc + 1) * KC, t0, s0, tid, QHb);
                } else if (st < tt) {
                    load_q_chunk(sb, 0, 0, t0, s0 + TSN, tid, QHb);
                } else if (rep + 1 < nrep) {
                    load_q_chunk(sb, 0, 0, tts[rep + 1] * TM, 0, tid, QHb);
                }
                if (cc == 0) load_v_tile(sb, s0, tid, VHb);
                CP_COMMIT();

                const uint32_t qb = sb + (uint32_t)(cc & 1) * 65536u;
#pragma unroll
                for (int ks = 0; ks < 8; ++ks) {
                    const uint32_t qtb = qb + (uint32_t)((ks >> 2) * 16384);
                    const uint32_t qsb = qb + 32768u + (uint32_t)((ks >> 2) * 16384);
                    const int kb = (ks & 3) * 32 + lgrp * 16;
                    uint32_t a0, a1, a2, a3;
                    ldsm4(a0, a1, a2, a3,
                          qtb + swz((uint32_t)((w16 + lrow) * 128 + kb)));
#pragma unroll
                    for (int sg = 0; sg < 8; ++sg) {
                        if (diag && sg > w) continue;   // fully-masked s-blocks
                        uint32_t r0, r1, r2, r3;
                        ldsm4(r0, r1, r2, r3,
                              qsb + swz((uint32_t)((sg * 16 + lrow) * 128 + kb)));
                        mma_fp16(Sacc[2 * sg],     a0, a1, a2, a3, r0, r2);
                        mma_fp16(Sacc[2 * sg + 1], a0, a1, a2, a3, r1, r3);
                    }
                }
            }

            // ---- in-register: mask + fp16-pack S C-frags into A-frags ----
            uint32_t A2[8][4];
            if (diag) {
                const int rA = t0 + w16 + qr;
                const int rB = rA + 8;
#pragma unroll
                for (int j = 0; j < 16; ++j) {
                    const int sc = s0 + 8 * j + qc;
                    if (sc     >= rA) Sacc[j][0] = 0.0f;
                    if (sc + 1 >= rA) Sacc[j][1] = 0.0f;
                    if (sc     >= rB) Sacc[j][2] = 0.0f;
                    if (sc + 1 >= rB) Sacc[j][3] = 0.0f;
                }
            }
#pragma unroll
            for (int jj = 0; jj < 8; ++jj) {
                A2[jj][0] = pack_h2(Sacc[2 * jj][0],     Sacc[2 * jj][1]);
                A2[jj][1] = pack_h2(Sacc[2 * jj][2],     Sacc[2 * jj][3]);
                A2[jj][2] = pack_h2(Sacc[2 * jj + 1][0], Sacc[2 * jj + 1][1]);
                A2[jj][3] = pack_h2(Sacc[2 * jj + 1][2], Sacc[2 * jj + 1][3]);
            }

            // ---- stage 2: O += S @ V^T (S in regs, V in smem) ----
#pragma unroll
            for (int jj = 0; jj < 8; ++jj) {
                if (diag && jj > w) continue;           // all-zero S k-blocks
                const uint32_t tV = sb + SM_V + (uint32_t)((jj >> 2) * 16384);
                const int kb = (jj & 3) * 32 + lgrp * 16;
#pragma unroll
                for (int dg = 0; dg < 8; ++dg) {
                    uint32_t r0, r1, r2, r3;
                    ldsm4(r0, r1, r2, r3,
                          tV + swz((uint32_t)((dg * 16 + lrow) * 128 + kb)));
                    mma_fp16(Oacc[2 * dg],     A2[jj][0], A2[jj][1], A2[jj][2],
                             A2[jj][3], r0, r2);
                    mma_fp16(Oacc[2 * dg + 1], A2[jj][0], A2[jj][1], A2[jj][2],
                             A2[jj][3], r1, r3);
                }
            }
            // no barrier: next s-tile's first barrier precedes any smem write
        }

        // ---- O writeback for this t-tile ----
        const int rA = t0 + w16 + qr;
        const int rB = rA + 8;
#pragma unroll
        for (int j = 0; j < 16; ++j) {
            const int d = 8 * j + qc;
            *(float2*)(Ob + (size_t)rA * D_ + d) = make_float2(Oacc[j][0], Oacc[j][1]);
            *(float2*)(Ob + (size_t)rB * D_ + d) = make_float2(Oacc[j][2], Oacc[j][3]);
        }
    }
}

// ---------------------------------------------------------------------------
extern "C" void kernel_launch(void* const* d_in, const int* in_sizes, int n_in,
                              void* d_out, int out_size) {
    const float* Q = (const float*)d_in[0];
    const float* V = (const float*)d_in[2];   // d_in[1] is K == Q
    float* O = (float*)d_out;

    const uint32_t n4 = (uint32_t)BH * T_ * (N_ / 4);
    rope_split_kernel<<<(n4 + NTH - 1) / NTH, NTH>>>(Q);

    dim3 tgrid(T_ / 32, D_ / 32, BH);
    vt_split_kernel<<<tgrid, dim3(32, 8)>>>(V);

    cudaFuncSetAttribute(attn_mma_kernel,
                         cudaFuncAttributeMaxDynamicSharedMemorySize, SM_TOT);
    attn_mma_kernel<<<9 * BH, NTH, SM_TOT>>>(O);
}

// round 11
// speedup vs baseline: 4.5904x; 1.0844x over previous
#include <cuda_runtime.h>
#include <cuda_fp16.h>
#include <cstdint>

#define BH   16
#define T_   2048
#define N_   1024
#define D_   128
#define TM   128          // t-rows per CTA tile
#define TSN  128          // s-cols per CTA tile
#define KC   128          // k-chunk (fp16 elems)
#define NCH  8            // N_/KC
#define NTT  16           // T_/TM
#define NTH  256

#define NB_ROPE 32768     // rope part: BH*T_*(N_/4) / 256
#define NB_VT   4096      // vt part:   (T_/32)*(D_/32)*BH

// ---------------- global scratch (static device alloc — allowed) ----------
__device__ __half g_QH[(size_t)BH * T_ * N_];   // 64 MiB (RoPE'd Q, fp16)
__device__ __half g_VTH[(size_t)BH * D_ * T_];  //  8 MiB (V^T, fp16)

// ---------------- helpers --------------------------------------------------
__device__ __forceinline__ uint32_t smem_u32(const void* p) {
    uint32_t a;
    asm("{ .reg .u64 t; cvta.to.shared.u64 t, %1; cvt.u32.u64 %0, t; }"
        : "=r"(a) : "l"(p));
    return a;
}
__device__ __forceinline__ uint32_t swz(uint32_t off) {   // SW128 swizzle
    return off ^ ((off >> 3) & 0x70);
}
__device__ __forceinline__ void cp16(uint32_t sdst, const void* g) {
    asm volatile("cp.async.cg.shared.global [%0], [%1], 16;\n"
                 :: "r"(sdst), "l"(g) : "memory");
}
#define CP_COMMIT() asm volatile("cp.async.commit_group;\n" ::: "memory")
#define CP_WAIT0()  asm volatile("cp.async.wait_group 0;\n" ::: "memory")

__device__ __forceinline__ void ldsm4(uint32_t& r0, uint32_t& r1,
                                      uint32_t& r2, uint32_t& r3, uint32_t a) {
    asm volatile("ldmatrix.sync.aligned.m8n8.x4.shared.b16 {%0,%1,%2,%3}, [%4];"
                 : "=r"(r0), "=r"(r1), "=r"(r2), "=r"(r3) : "r"(a));
}
__device__ __forceinline__ void mma_fp16(float c[4],
        uint32_t a0, uint32_t a1, uint32_t a2, uint32_t a3,
        uint32_t b0, uint32_t b1) {
    asm volatile(
        "mma.sync.aligned.m16n8k16.row.col.f32.f16.f16.f32 "
        "{%0,%1,%2,%3}, {%4,%5,%6,%7}, {%8,%9}, {%0,%1,%2,%3};"
        : "+f"(c[0]), "+f"(c[1]), "+f"(c[2]), "+f"(c[3])
        : "r"(a0), "r"(a1), "r"(a2), "r"(a3), "r"(b0), "r"(b1));
}
__device__ __forceinline__ uint32_t pack_h2(float lo, float hi) {
    __half2 h = __floats2half2_rn(lo, hi);
    return *reinterpret_cast<uint32_t*>(&h);
}

// ---------------- merged prep: RoPE (rope blocks) + V^T (vt blocks) -------
__global__ void prep_kernel(const float* __restrict__ Q,
                            const float* __restrict__ V) {
    __shared__ float tile[32][33];
    const uint32_t bid = blockIdx.x;
    const int tid = threadIdx.x;

    if (bid < NB_ROPE) {
        // ---- RoPE + fp16 quantize, 2 pairs (1 float4) per thread ----
        uint32_t i4 = bid * NTH + tid;
        uint32_t p0 = 2u * i4;                 // first pair index
        uint32_t n2 = p0 & 511u;               // N_/2 = 512 pairs per row
        uint32_t t  = (p0 >> 9) & 2047u;

        const float4 q = ((const float4*)Q)[i4];
        float tf = (float)t;

        float pos0 = (float)(2u * n2);
        float f0 = exp2f(-16.0f * pos0 * (1.0f / (float)N_)) * 0.15915494309189535f;
        float r0 = tf * f0;
        float ph0 = (r0 - floorf(r0)) * 6.283185307179586f;
        float s0, c0; __sincosf(ph0, &s0, &c0);

        float pos1 = (float)(2u * (n2 + 1u));
        float f1 = exp2f(-16.0f * pos1 * (1.0f / (float)N_)) * 0.15915494309189535f;
        float r1 = tf * f1;
        float ph1 = (r1 - floorf(r1)) * 6.283185307179586f;
        float s1, c1; __sincosf(ph1, &s1, &c1);

        uint2 o;
        o.x = pack_h2(q.x * c0 - q.y * s0, q.y * c0 + q.x * s0);
        o.y = pack_h2(q.z * c1 - q.w * s1, q.w * c1 + q.z * s1);
        ((uint2*)g_QH)[i4] = o;
    } else {
        // ---- coalesced tiled V transpose + fp16 quantize ----
        const uint32_t vb = bid - NB_ROPE;
        const int t0 = (int)(vb & 63u) * 32;        // T_/32 = 64
        const int d0 = (int)((vb >> 6) & 3u) * 32;  // D_/32 = 4
        const int bh = (int)(vb >> 8);
        const int tx = tid & 31, ty = tid >> 5;     // (32, 8)

        const float* Vb = V + ((size_t)bh * T_) * D_;
#pragma unroll
        for (int i = 0; i < 4; ++i)
            tile[ty + i * 8][tx] = Vb[(size_t)(t0 + ty + i * 8) * D_ + d0 + tx];
        __syncthreads();

        __half* VTb = g_VTH + (size_t)bh * D_ * T_;
#pragma unroll
        for (int i = 0; i < 4; ++i)
            VTb[(size_t)(d0 + ty + i * 8) * T_ + t0 + tx] =
                __float2half(tile[tx][ty + i * 8]);
    }
}

// ---------------- attention (mma.sync fp16, reg-resident S) ---------------
// smem map (bytes):
//   [0, 128K)    : Q chunk double buffer, buf b at b*65536:
//                  Qt_sub0(+0) Qt_sub1(+16K) Qs_sub0(+32K) Qs_sub1(+48K)
//                  each subtile [128 rows][64 k] fp16, SW128
//   [128K, 160K) : V tile: V_sub0(+0) V_sub1(+16K), [128 d][64 s] each
#define SM_V   131072
#define SM_TOT 163840

__device__ __forceinline__ void load_q_chunk(
    uint32_t sb, int buf, int k0, int t0, int s0, int tid,
    const __half* QHb) {
    int tsel = tid >> 7;        // 0: Qt, 1: Qs
    int u    = tid & 127;
    const __half* src = QHb + (size_t)(tsel ? s0 : t0) * N_ + k0;
    uint32_t tb = sb + (uint32_t)buf * 65536u + (uint32_t)tsel * 32768u;
#pragma unroll
    for (int i = 0; i < 16; ++i) {
        int idx = u * 16 + i;              // 0..2047 (16B units), 16/row
        int r = idx >> 4, c16 = idx & 15;
        cp16(tb + (uint32_t)((c16 >> 3) * 16384) +
                 swz((uint32_t)(r * 128 + (c16 & 7) * 16)),
             src + (size_t)r * N_ + c16 * 8);
    }
}

__device__ __forceinline__ void load_v_tile(
    uint32_t sb, int s0, int tid, const __half* VHb) {
    int u = tid;
#pragma unroll
    for (int i = 0; i < 8; ++i) {
        int idx = u * 8 + i;               // 0..2047 (16B units), 16/row
        int r = idx >> 4, c16 = idx & 15;
        cp16(sb + SM_V + (uint32_t)((c16 >> 3) * 16384) +
                 swz((uint32_t)(r * 128 + (c16 & 7) * 16)),
             VHb + (size_t)r * T_ + s0 + c16 * 8);
    }
}

__global__ void __launch_bounds__(NTH)
attn_mma_kernel(float* __restrict__ O) {
    extern __shared__ char smem[];
    uint32_t sb = smem_u32(smem);
    const int tid  = threadIdx.x;
    const int w    = tid >> 5;        // warp 0..7: owns t-rows [16w, 16w+16)
    const int lane = tid & 31;
    const int lrow = lane & 15;       // ldmatrix row-within-16
    const int lgrp = lane >> 4;       // ldmatrix 16B-column select
    const int qr   = lane >> 2;       // C/A-frag row within 8
    const int qc   = (lane & 3) << 1; // C/A-frag col pair

    const int bh = blockIdx.x / 9;
    const int c  = blockIdx.x % 9;

    int tts[2]; int nrep;
    if (c == 0)      { tts[0] = 15; tts[1] = 15; nrep = 1; }
    else if (c == 8) { tts[0] = 7;  tts[1] = 7;  nrep = 1; }
    else             { tts[0] = 15 - c; tts[1] = c - 1; nrep = 2; }

    const __half* QHb = g_QH  + (size_t)bh * T_ * N_;
    const __half* VHb = g_VTH + (size_t)bh * D_ * T_;
    float* Ob = O + (size_t)bh * T_ * D_;

    const int w16 = w * 16;

    // prologue: chunk0 of first s-tile into buf0
    load_q_chunk(sb, 0, 0, tts[0] * TM, 0, tid, QHb);
    CP_COMMIT();

    for (int rep = 0; rep < nrep; ++rep) {
        const int tt = tts[rep];
        const int t0 = tt * TM;

        float Oacc[16][4];
#pragma unroll
        for (int b = 0; b < 16; ++b)
#pragma unroll
            for (int x = 0; x < 4; ++x) Oacc[b][x] = 0.0f;

        for (int st = 0; st <= tt; ++st) {
            const int s0 = st * TSN;
            const bool diag = (st == tt);

            float Sacc[16][4];
#pragma unroll
            for (int b = 0; b < 16; ++b)
#pragma unroll
                for (int x = 0; x < 4; ++x) Sacc[b][x] = 0.0f;

            // ---- stage 1: S = Qt @ Qs^T, 8 double-buffered K=128 chunks --
            for (int cc = 0; cc < NCH; ++cc) {
                CP_WAIT0();
                __syncthreads();
                // issue next loads AFTER the barrier (WAR-safe)
                if (cc + 1 < NCH) {
                    load_q_chunk(sb, (cc + 1) & 1, (cc + 1) * KC, t0, s0, tid, QHb);
                } else if (st < tt) {
                    load_q_chunk(sb, 0, 0, t0, s0 + TSN, tid, QHb);
                } else if (rep + 1 < nrep) {
                    load_q_chunk(sb, 0, 0, tts[rep + 1] * TM, 0, tid, QHb);
                }
                if (cc == 0) load_v_tile(sb, s0, tid, VHb);
                CP_COMMIT();

                const uint32_t qb = sb + (uint32_t)(cc & 1) * 65536u;
#pragma unroll
                for (int ks = 0; ks < 8; ++ks) {
                    const uint32_t qtb = qb + (uint32_t)((ks >> 2) * 16384);
                    const uint32_t qsb = qb + 32768u + (uint32_t)((ks >> 2) * 16384);
                    const int kb = (ks & 3) * 32 + lgrp * 16;
                    uint32_t a0, a1, a2, a3;
                    ldsm4(a0, a1, a2, a3,
                          qtb + swz((uint32_t)((w16 + lrow) * 128 + kb)));
                    if (!diag) {
                        // software-pipelined B loads: fetch sg+1 during sg MMAs
                        uint32_t bA[4], bB[4];
                        ldsm4(bA[0], bA[1], bA[2], bA[3],
                              qsb + swz((uint32_t)(lrow * 128 + kb)));
#pragma unroll
                        for (int sg = 0; sg < 8; ++sg) {
                            uint32_t* bc = (sg & 1) ? bB : bA;
                            uint32_t* bn = (sg & 1) ? bA : bB;
                            if (sg < 7)
                                ldsm4(bn[0], bn[1], bn[2], bn[3],
                                      qsb + swz((uint32_t)(((sg + 1) * 16 + lrow) * 128 + kb)));
                            mma_fp16(Sacc[2 * sg],     a0, a1, a2, a3, bc[0], bc[2]);
                            mma_fp16(Sacc[2 * sg + 1], a0, a1, a2, a3, bc[1], bc[3]);
                        }
                    } else {
#pragma unroll
                        for (int sg = 0; sg < 8; ++sg) {
                            if (sg > w) continue;       // fully-masked s-blocks
                            uint32_t r0, r1, r2, r3;
                            ldsm4(r0, r1, r2, r3,
                                  qsb + swz((uint32_t)((sg * 16 + lrow) * 128 + kb)));
                            mma_fp16(Sacc[2 * sg],     a0, a1, a2, a3, r0, r2);
                            mma_fp16(Sacc[2 * sg + 1], a0, a1, a2, a3, r1, r3);
                        }
                    }
                }
            }

            // ---- in-register: mask + fp16-pack S C-frags into A-frags ----
            uint32_t A2[8][4];
            if (diag) {
                const int rA = t0 + w16 + qr;
                const int rB = rA + 8;
#pragma unroll
                for (int j = 0; j < 16; ++j) {
                    const int sc = s0 + 8 * j + qc;
                    if (sc     >= rA) Sacc[j][0] = 0.0f;
                    if (sc + 1 >= rA) Sacc[j][1] = 0.0f;
                    if (sc     >= rB) Sacc[j][2] = 0.0f;
                    if (sc + 1 >= rB) Sacc[j][3] = 0.0f;
                }
            }
#pragma unroll
            for (int jj = 0; jj < 8; ++jj) {
                A2[jj][0] = pack_h2(Sacc[2 * jj][0],     Sacc[2 * jj][1]);
                A2[jj][1] = pack_h2(Sacc[2 * jj][2],     Sacc[2 * jj][3]);
                A2[jj][2] = pack_h2(Sacc[2 * jj + 1][0], Sacc[2 * jj + 1][1]);
                A2[jj][3] = pack_h2(Sacc[2 * jj + 1][2], Sacc[2 * jj + 1][3]);
            }

            // ---- stage 2: O += S @ V^T (S in regs, V in smem) ----
#pragma unroll
            for (int jj = 0; jj < 8; ++jj) {
                if (diag && jj > w) continue;           // all-zero S k-blocks
                const uint32_t tV = sb + SM_V + (uint32_t)((jj >> 2) * 16384);
                const int kb = (jj & 3) * 32 + lgrp * 16;
                // software-pipelined V-frag loads
                uint32_t bA[4], bB[4];
                ldsm4(bA[0], bA[1], bA[2], bA[3],
                      tV + swz((uint32_t)(lrow * 128 + kb)));
#pragma unroll
                for (int dg = 0; dg < 8; ++dg) {
                    uint32_t* bc = (dg & 1) ? bB : bA;
                    uint32_t* bn = (dg & 1) ? bA : bB;
                    if (dg < 7)
                        ldsm4(bn[0], bn[1], bn[2], bn[3],
                              tV + swz((uint32_t)(((dg + 1) * 16 + lrow) * 128 + kb)));
                    mma_fp16(Oacc[2 * dg],     A2[jj][0], A2[jj][1], A2[jj][2],
                             A2[jj][3], bc[0], bc[2]);
                    mma_fp16(Oacc[2 * dg + 1], A2[jj][0], A2[jj][1], A2[jj][2],
                             A2[jj][3], bc[1], bc[3]);
                }
            }
            // no barrier: next s-tile's first barrier precedes any smem write
        }

        // ---- O writeback for this t-tile ----
        const int rA = t0 + w16 + qr;
        const int rB = rA + 8;
#pragma unroll
        for (int j = 0; j < 16; ++j) {
            const int d = 8 * j + qc;
            *(float2*)(Ob + (size_t)rA * D_ + d) = make_float2(Oacc[j][0], Oacc[j][1]);
            *(float2*)(Ob + (size_t)rB * D_ + d) = make_float2(Oacc[j][2], Oacc[j][3]);
        }
    }
}

// ---------------------------------------------------------------------------
extern "C" void kernel_launch(void* const* d_in, const int* in_sizes, int n_in,
                              void* d_out, int out_size) {
    const float* Q = (const float*)d_in[0];
    const float* V = (const float*)d_in[2];   // d_in[1] is K == Q
    float* O = (float*)d_out;

    prep_kernel<<<NB_ROPE + NB_VT, NTH>>>(Q, V);

    cudaFuncSetAttribute(attn_mma_kernel,
                         cudaFuncAttributeMaxDynamicSharedMemorySize, SM_TOT);
    attn_mma_kernel<<<9 * BH, NTH, SM_TOT>>>(O);
}